// round 1
// baseline (speedup 1.0000x reference)
#include <cuda_runtime.h>
#include <cuda_bf16.h>

// Problem constants
#define BB 16
#define NN 512
#define FF 625
#define FH 937

// Scratch (no allocs allowed -> device globals)
__device__ float g_L[(size_t)BB * NN * NN];    // adjacency -> normalized L
__device__ float g_T[(size_t)BB * NN * FH];    // t1 = L@X (625) then L@h (937)
__device__ float g_h[(size_t)BB * NN * FH];    // hidden layer

// ---------------------------------------------------------------------------
// Kernel 1: thresholded adjacency.
// grid (8, 8, 16), block 256. Each block computes a 64x64 tile of
// D[b,i,j] = sum_f |X[b,i,f]-X[b,j,f]|, then writes A = (D<=180 && |ai-aj|<=0.05).
// Diagonal naturally lands at 1 (D=0), matching A*(1-I)+I of the reference.
// ---------------------------------------------------------------------------
__global__ __launch_bounds__(256) void adj_kernel(
    const float* __restrict__ X, const float* __restrict__ att,
    float* __restrict__ A)
{
    __shared__ float sXi[32][68];
    __shared__ float sXj[32][68];

    const int b  = blockIdx.z;
    const int i0 = blockIdx.y * 64;
    const int j0 = blockIdx.x * 64;
    const float* Xb = X + (size_t)b * NN * FF;

    const int tid = threadIdx.x;
    const int tx = tid & 15;          // j sub-tile
    const int ty = tid >> 4;          // i sub-tile

    float acc[4][4];
#pragma unroll
    for (int r = 0; r < 4; ++r)
#pragma unroll
        for (int c = 0; c < 4; ++c) acc[r][c] = 0.f;

    const int lk = tid & 31;          // k within tile
    const int lr = tid >> 5;          // row group (8 rows per pass)

    for (int k0 = 0; k0 < FF; k0 += 32) {
#pragma unroll
        for (int r = 0; r < 8; ++r) {
            const int row = lr + r * 8;
            const int k = k0 + lk;
            float vi = 0.f, vj = 0.f;
            if (k < FF) {
                vi = Xb[(size_t)(i0 + row) * FF + k];
                vj = Xb[(size_t)(j0 + row) * FF + k];
            }
            sXi[lk][row] = vi;
            sXj[lk][row] = vj;
        }
        __syncthreads();
#pragma unroll
        for (int kk = 0; kk < 32; ++kk) {
            const float4 av = *(const float4*)&sXi[kk][ty * 4];
            const float4 bv = *(const float4*)&sXj[kk][tx * 4];
            const float a_[4] = {av.x, av.y, av.z, av.w};
            const float b_[4] = {bv.x, bv.y, bv.z, bv.w};
#pragma unroll
            for (int r = 0; r < 4; ++r)
#pragma unroll
                for (int c = 0; c < 4; ++c)
                    acc[r][c] += fabsf(a_[r] - b_[c]);
        }
        __syncthreads();
    }

    const float* attb = att + b * NN;
    float ai[4], aj[4];
#pragma unroll
    for (int r = 0; r < 4; ++r) ai[r] = attb[i0 + ty * 4 + r];
#pragma unroll
    for (int c = 0; c < 4; ++c) aj[c] = attb[j0 + tx * 4 + c];

    float* Ab = A + (size_t)b * NN * NN;
#pragma unroll
    for (int r = 0; r < 4; ++r) {
        const int i = i0 + ty * 4 + r;
#pragma unroll
        for (int c = 0; c < 4; ++c) {
            const int j = j0 + tx * 4 + c;
            const float keep =
                (acc[r][c] <= 180.0f && fabsf(ai[r] - aj[c]) <= 0.05f) ? 1.f : 0.f;
            Ab[(size_t)i * NN + j] = keep;
        }
    }
}

// ---------------------------------------------------------------------------
// Kernel 2: row normalization L = D^-1 A. One block (256 thr) per row of 512.
// Degrees are sums of 0/1 -> exact regardless of order.
// ---------------------------------------------------------------------------
__global__ __launch_bounds__(256) void norm_kernel(float* __restrict__ L)
{
    const size_t row = blockIdx.x;
    float* p = L + row * NN;
    const int t = threadIdx.x;

    float v0 = p[t];
    float v1 = p[t + 256];
    float v = v0 + v1;
#pragma unroll
    for (int o = 16; o; o >>= 1) v += __shfl_down_sync(0xffffffffu, v, o);

    __shared__ float swarp[8];
    __shared__ float sdinv;
    if ((t & 31) == 0) swarp[t >> 5] = v;
    __syncthreads();
    if (t == 0) {
        float d = 0.f;
#pragma unroll
        for (int w = 0; w < 8; ++w) d += swarp[w];
        sdinv = 1.0f / d;   // deg >= 1 always (diagonal)
    }
    __syncthreads();
    const float dinv = sdinv;
    p[t]       = v0 * dinv;
    p[t + 256] = v1 * dinv;
}

// ---------------------------------------------------------------------------
// Kernel 3: generic batched SGEMM, 64x64x16 tiles, 4x4 register tile.
// C[b] = op( A1[b]@B1 (+ A2[b]@B2 if dual) + bias ), op = relu optionally.
// A row-major MxK, B row-major KxN (sB=0 => shared weights), C row-major MxN.
// ---------------------------------------------------------------------------
__global__ __launch_bounds__(256) void gemm_kernel(
    const float* __restrict__ A1, const float* __restrict__ A2,
    const float* __restrict__ B1, const float* __restrict__ B2,
    const float* __restrict__ bias, float* __restrict__ C,
    int M, int N, int K,
    long sA, long sB, long sC, int dual, int relu)
{
    __shared__ float sAm[16][68];
    __shared__ float sBm[16][68];

    const int b  = blockIdx.z;
    const int m0 = blockIdx.y * 64;
    const int n0 = blockIdx.x * 64;
    const int tid = threadIdx.x;
    const int tx = tid & 15;
    const int ty = tid >> 4;

    float acc[4][4];
#pragma unroll
    for (int r = 0; r < 4; ++r)
#pragma unroll
        for (int c = 0; c < 4; ++c) acc[r][c] = 0.f;

    const int la_k = tid & 15;    // A: k within tile
    const int la_m = tid >> 4;    // A: m group (16 rows/pass)
    const int lb_n = tid & 63;    // B: n within tile
    const int lb_k = tid >> 6;    // B: k group (4 rows/pass)

    const int npair = dual ? 2 : 1;
    for (int pair = 0; pair < npair; ++pair) {
        const float* Ab = (pair ? A2 : A1) + (long)b * sA;
        const float* Bb = (pair ? B2 : B1) + (long)b * sB;

        for (int k0 = 0; k0 < K; k0 += 16) {
#pragma unroll
            for (int r = 0; r < 4; ++r) {
                const int m = la_m + r * 16;
                const int k = k0 + la_k;
                sAm[la_k][m] = (k < K) ? Ab[(size_t)(m0 + m) * K + k] : 0.f;
            }
#pragma unroll
            for (int r = 0; r < 4; ++r) {
                const int k = k0 + lb_k + r * 4;
                const int n = n0 + lb_n;
                sBm[lb_k + r * 4][lb_n] =
                    (k < K && n < N) ? Bb[(size_t)k * N + n] : 0.f;
            }
            __syncthreads();
#pragma unroll
            for (int kk = 0; kk < 16; ++kk) {
                const float4 av = *(const float4*)&sAm[kk][ty * 4];
                const float4 bv = *(const float4*)&sBm[kk][tx * 4];
                const float a_[4] = {av.x, av.y, av.z, av.w};
                const float b_[4] = {bv.x, bv.y, bv.z, bv.w};
#pragma unroll
                for (int r = 0; r < 4; ++r)
#pragma unroll
                    for (int c = 0; c < 4; ++c)
                        acc[r][c] += a_[r] * b_[c];
            }
            __syncthreads();
        }
    }

    float* Cb = C + (long)b * sC;
#pragma unroll
    for (int r = 0; r < 4; ++r) {
        const int m = m0 + ty * 4 + r;
        if (m >= M) continue;
#pragma unroll
        for (int c = 0; c < 4; ++c) {
            const int n = n0 + tx * 4 + c;
            if (n >= N) continue;
            float v = acc[r][c];
            if (bias) v += bias[n];
            if (relu) v = fmaxf(v, 0.f);
            Cb[(size_t)m * N + n] = v;
        }
    }
}

extern "C" void kernel_launch(void* const* d_in, const int* in_sizes, int n_in,
                              void* d_out, int out_size)
{
    const float* x4  = (const float*)d_in[0];   // [16,512,25,25] -> [16,512,625]
    const float* att = (const float*)d_in[1];   // [16,512,1,1]
    const float* W1  = (const float*)d_in[2];   // [2,625,937]
    const float* b1  = (const float*)d_in[3];   // [937]
    const float* W2  = (const float*)d_in[4];   // [2,937,625]
    const float* b2  = (const float*)d_in[5];   // [625]
    float* out = (float*)d_out;

    void *pL, *pT, *ph;
    cudaGetSymbolAddress(&pL, g_L);
    cudaGetSymbolAddress(&pT, g_T);
    cudaGetSymbolAddress(&ph, g_h);
    float* L = (float*)pL;
    float* T = (float*)pT;
    float* h = (float*)ph;

    // 1) adjacency
    adj_kernel<<<dim3(8, 8, BB), 256>>>(x4, att, L);
    // 2) row normalize
    norm_kernel<<<dim3(BB * NN), 256>>>(L);

    // 3) T = L @ X   (M=512, N=625, K=512)
    gemm_kernel<<<dim3(10, 8, BB), 256>>>(
        L, L, x4, x4, nullptr, T,
        NN, FF, NN,
        (long)NN * NN, (long)NN * FF, (long)NN * FF, 0, 0);

    // 4) h = relu(X@W1[0] + T@W1[1] + b1)   (M=512, N=937, K=625)
    gemm_kernel<<<dim3(15, 8, BB), 256>>>(
        x4, T, W1, W1 + (size_t)FF * FH, b1, h,
        NN, FH, FF,
        (long)NN * FF, 0, (long)NN * FH, 1, 1);

    // 5) T = L @ h   (M=512, N=937, K=512)
    gemm_kernel<<<dim3(15, 8, BB), 256>>>(
        L, L, h, h, nullptr, T,
        NN, FH, NN,
        (long)NN * NN, (long)NN * FH, (long)NN * FH, 0, 0);

    // 6) out = relu(h@W2[0] + T@W2[1] + b2)   (M=512, N=625, K=937)
    gemm_kernel<<<dim3(10, 8, BB), 256>>>(
        h, T, W2, W2 + (size_t)FH * FF, b2, out,
        NN, FF, FH,
        (long)NN * FH, 0, (long)NN * FF, 1, 1);
}

// round 3
// speedup vs baseline: 1.8220x; 1.8220x over previous
#include <cuda_runtime.h>
#include <cuda_bf16.h>
#include <cstdint>

#define BB 16
#define NN 512
#define FF 625
#define FH 937
#define FFP 640      // F padded (mult of 128)
#define FHPN 1024    // Fh padded for N-dim (mult of 128)
#define FHPK 944     // Fh padded for K-dim (mult of 16)

typedef __nv_bfloat16 bf16;

// ---------------- scratch (no allocs allowed -> device globals) -------------
__device__ float g_L[(size_t)BB * NN * NN];          // adjacency -> normalized L (fp32)

__device__ bf16 g_Xh[(size_t)BB * NN * FFP],  g_Xl[(size_t)BB * NN * FFP];
__device__ bf16 g_Lh[(size_t)BB * NN * NN],   g_Ll[(size_t)BB * NN * NN];
__device__ bf16 g_Th[(size_t)BB * NN * FFP],  g_Tl[(size_t)BB * NN * FFP];
__device__ bf16 g_hh[(size_t)BB * NN * FHPN], g_hl[(size_t)BB * NN * FHPN];
__device__ bf16 g_T2h[(size_t)BB * NN * FHPN], g_T2l[(size_t)BB * NN * FHPN];
__device__ bf16 g_W1h[2ul * FFP * FHPN],  g_W1l[2ul * FFP * FHPN];
__device__ bf16 g_W2h[2ul * FHPK * FFP],  g_W2l[2ul * FHPK * FFP];
__device__ float g_b1p[FHPN], g_b2p[FFP];

// ---------------------------------------------------------------------------
// Kernel 1: thresholded adjacency (unchanged from R1 — known good).
// ---------------------------------------------------------------------------
__global__ __launch_bounds__(256) void adj_kernel(
    const float* __restrict__ X, const float* __restrict__ att,
    float* __restrict__ A)
{
    __shared__ float sXi[32][68];
    __shared__ float sXj[32][68];

    const int b  = blockIdx.z;
    const int i0 = blockIdx.y * 64;
    const int j0 = blockIdx.x * 64;
    const float* Xb = X + (size_t)b * NN * FF;

    const int tid = threadIdx.x;
    const int tx = tid & 15;
    const int ty = tid >> 4;

    float acc[4][4];
#pragma unroll
    for (int r = 0; r < 4; ++r)
#pragma unroll
        for (int c = 0; c < 4; ++c) acc[r][c] = 0.f;

    const int lk = tid & 31;
    const int lr = tid >> 5;

    for (int k0 = 0; k0 < FF; k0 += 32) {
#pragma unroll
        for (int r = 0; r < 8; ++r) {
            const int row = lr + r * 8;
            const int k = k0 + lk;
            float vi = 0.f, vj = 0.f;
            if (k < FF) {
                vi = Xb[(size_t)(i0 + row) * FF + k];
                vj = Xb[(size_t)(j0 + row) * FF + k];
            }
            sXi[lk][row] = vi;
            sXj[lk][row] = vj;
        }
        __syncthreads();
#pragma unroll
        for (int kk = 0; kk < 32; ++kk) {
            const float4 av = *(const float4*)&sXi[kk][ty * 4];
            const float4 bv = *(const float4*)&sXj[kk][tx * 4];
            const float a_[4] = {av.x, av.y, av.z, av.w};
            const float b_[4] = {bv.x, bv.y, bv.z, bv.w};
#pragma unroll
            for (int r = 0; r < 4; ++r)
#pragma unroll
                for (int c = 0; c < 4; ++c)
                    acc[r][c] += fabsf(a_[r] - b_[c]);
        }
        __syncthreads();
    }

    const float* attb = att + b * NN;
    float ai[4], aj[4];
#pragma unroll
    for (int r = 0; r < 4; ++r) ai[r] = attb[i0 + ty * 4 + r];
#pragma unroll
    for (int c = 0; c < 4; ++c) aj[c] = attb[j0 + tx * 4 + c];

    float* Ab = A + (size_t)b * NN * NN;
#pragma unroll
    for (int r = 0; r < 4; ++r) {
        const int i = i0 + ty * 4 + r;
#pragma unroll
        for (int c = 0; c < 4; ++c) {
            const int j = j0 + tx * 4 + c;
            const float keep =
                (acc[r][c] <= 180.0f && fabsf(ai[r] - aj[c]) <= 0.05f) ? 1.f : 0.f;
            Ab[(size_t)i * NN + j] = keep;
        }
    }
}

// ---------------------------------------------------------------------------
// Kernel 2: row normalization L = D^-1 A (unchanged).
// ---------------------------------------------------------------------------
__global__ __launch_bounds__(256) void norm_kernel(float* __restrict__ L)
{
    const size_t row = blockIdx.x;
    float* p = L + row * NN;
    const int t = threadIdx.x;

    float v0 = p[t];
    float v1 = p[t + 256];
    float v = v0 + v1;
#pragma unroll
    for (int o = 16; o; o >>= 1) v += __shfl_down_sync(0xffffffffu, v, o);

    __shared__ float swarp[8];
    __shared__ float sdinv;
    if ((t & 31) == 0) swarp[t >> 5] = v;
    __syncthreads();
    if (t == 0) {
        float d = 0.f;
#pragma unroll
        for (int w = 0; w < 8; ++w) d += swarp[w];
        sdinv = 1.0f / d;
    }
    __syncthreads();
    const float dinv = sdinv;
    p[t]       = v0 * dinv;
    p[t + 256] = v1 * dinv;
}

// ---------------------------------------------------------------------------
// Split fp32 -> (hi, lo) bf16 pair into zero-padded buffers.
// ---------------------------------------------------------------------------
__global__ __launch_bounds__(256) void split_kernel(
    const float* __restrict__ src, bf16* __restrict__ dh, bf16* __restrict__ dl,
    int R, int C, int Cp, long totalP, long sStride, long dStride)
{
    long idx = (long)blockIdx.x * 256 + threadIdx.x;
    if (idx >= totalP) return;
    const int b = blockIdx.y;
    const int r = (int)(idx / Cp);
    const int c = (int)(idx % Cp);
    float v = (r < R && c < C) ? src[(long)b * sStride + (long)r * C + c] : 0.f;
    bf16 hi = __float2bfloat16(v);
    float lo = v - __bfloat162float(hi);
    dh[(long)b * dStride + idx] = hi;
    dl[(long)b * dStride + idx] = __float2bfloat16(lo);
}

__global__ void biaspad_kernel(const float* __restrict__ b1, const float* __restrict__ b2)
{
    int t = blockIdx.x * 256 + threadIdx.x;
    if (t < FHPN) g_b1p[t] = (t < FH) ? b1[t] : 0.f;
    if (t < FFP)  g_b2p[t] = (t < FF) ? b2[t] : 0.f;
}

// ---------------------------------------------------------------------------
// Tensor-core GEMM: C[b] = op( sum_seg A_seg[b] @ B_seg[b] + bias )
// Block tile 128x128, K-step 16, 8 warps (warp tile 64x32), bf16 mma.sync,
// cp.async double-buffered smem with xor swizzle for conflict-free ldmatrix.
// ---------------------------------------------------------------------------
struct GP {
    const bf16* A[6];
    const bf16* B[6];
    long sA[6], sB[6];
    int  K[6];
    int  nseg;
    int  ldA, ldB;
    float* Cf; bf16* Ch; bf16* Cl;
    long sC; int ldC;
    const float* bias;
    int relu, Nlim, splitOut;
};

__device__ __forceinline__ void cp16(uint32_t dst, const void* src) {
    asm volatile("cp.async.cg.shared.global [%0], [%1], 16;\n" :: "r"(dst), "l"(src));
}
__device__ __forceinline__ void ldsm4(uint32_t* r, uint32_t addr) {
    asm volatile("ldmatrix.sync.aligned.m8n8.x4.shared.b16 {%0,%1,%2,%3}, [%4];\n"
                 : "=r"(r[0]), "=r"(r[1]), "=r"(r[2]), "=r"(r[3]) : "r"(addr));
}
__device__ __forceinline__ void ldsm4t(uint32_t* r, uint32_t addr) {
    asm volatile("ldmatrix.sync.aligned.m8n8.x4.trans.shared.b16 {%0,%1,%2,%3}, [%4];\n"
                 : "=r"(r[0]), "=r"(r[1]), "=r"(r[2]), "=r"(r[3]) : "r"(addr));
}
__device__ __forceinline__ void mma16816(float* d, const uint32_t* a, uint32_t b0, uint32_t b1) {
    asm volatile(
        "mma.sync.aligned.m16n8k16.row.col.f32.bf16.bf16.f32 "
        "{%0,%1,%2,%3}, {%4,%5,%6,%7}, {%8,%9}, {%0,%1,%2,%3};\n"
        : "+f"(d[0]), "+f"(d[1]), "+f"(d[2]), "+f"(d[3])
        : "r"(a[0]), "r"(a[1]), "r"(a[2]), "r"(a[3]), "r"(b0), "r"(b1));
}

__global__ __launch_bounds__(256) void mma_gemm(GP p)
{
    __shared__ __align__(128) char smem[16384];  // A: [0,8K) 2 stages, B: [8K,16K)
    const uint32_t sbase = (uint32_t)__cvta_generic_to_shared(smem);

    const int tid  = threadIdx.x;
    const int lane = tid & 31;
    const int warp = tid >> 5;
    const int b  = blockIdx.z;
    const int m0 = blockIdx.y * 128;
    const int n0 = blockIdx.x * 128;
    const int wm = (warp & 1) * 64;
    const int wn = (warp >> 1) * 32;

    float acc[4][4][4];
#pragma unroll
    for (int i = 0; i < 4; ++i)
#pragma unroll
        for (int j = 0; j < 4; ++j)
#pragma unroll
            for (int k = 0; k < 4; ++k) acc[i][j][k] = 0.f;

    // producer indices (one 16B chunk each for A and B per thread)
    const int ar = tid >> 1, ac = tid & 1;     // A: 128 rows x 2 chunks
    const int bk = tid >> 4, bc = tid & 15;    // B: 16 rows x 16 chunks
    const uint32_t aDst = (uint32_t)((ar * 2 + (ac ^ ((ar >> 2) & 1))) * 16);
    const uint32_t bDst = (uint32_t)(8192 + (bk * 16 + (bc ^ (bk & 7))) * 16);

    // consumer (ldmatrix) byte offsets within a stage
    uint32_t aLd[4], bLd[2];
#pragma unroll
    for (int f = 0; f < 4; ++f) {
        const int r = wm + f * 16 + (lane & 15);
        const int c = (lane >> 4) & 1;
        aLd[f] = (uint32_t)((r * 2 + (c ^ ((r >> 2) & 1))) * 16);
    }
#pragma unroll
    for (int g = 0; g < 2; ++g) {
        const int k = lane & 15;
        const int cn = (wn >> 3) + g * 2 + ((lane >> 4) & 1);
        bLd[g] = (uint32_t)(8192 + (k * 16 + (cn ^ (k & 7))) * 16);
    }

    for (int seg = 0; seg < p.nseg; ++seg) {
        const bf16* Ag = p.A[seg] + (long)b * p.sA[seg] + (long)(m0 + ar) * p.ldA + ac * 8;
        const bf16* Bg = p.B[seg] + (long)b * p.sB[seg] + (long)bk * p.ldB + n0 + bc * 8;
        const int steps = p.K[seg] >> 4;

        cp16(sbase + aDst, Ag);
        cp16(sbase + bDst, Bg);
        asm volatile("cp.async.commit_group;\n");

        for (int s = 0; s < steps; ++s) {
            const uint32_t so = (uint32_t)((s & 1) * 4096);
            if (s + 1 < steps) {
                const uint32_t so2 = (uint32_t)(((s + 1) & 1) * 4096);
                cp16(sbase + so2 + aDst, Ag + (size_t)(s + 1) * 16);
                cp16(sbase + so2 + bDst, Bg + (size_t)(s + 1) * 16 * p.ldB);
                asm volatile("cp.async.commit_group;\n");
                asm volatile("cp.async.wait_group 1;\n");
            } else {
                asm volatile("cp.async.wait_group 0;\n");
            }
            __syncthreads();

            uint32_t afr[4][4], bfr[2][4];
#pragma unroll
            for (int f = 0; f < 4; ++f) ldsm4(afr[f], sbase + so + aLd[f]);
#pragma unroll
            for (int g = 0; g < 2; ++g) ldsm4t(bfr[g], sbase + so + bLd[g]);

#pragma unroll
            for (int mf = 0; mf < 4; ++mf)
#pragma unroll
                for (int nf = 0; nf < 4; ++nf) {
                    const uint32_t* bb = bfr[nf >> 1];
                    const int sub = (nf & 1) * 2;
                    mma16816(acc[mf][nf], afr[mf], bb[sub], bb[sub + 1]);
                }
            __syncthreads();
        }
    }

    // -------- epilogue --------
    const int row0 = m0 + wm;
    const int col0 = n0 + wn;
#pragma unroll
    for (int mf = 0; mf < 4; ++mf) {
#pragma unroll
        for (int nf = 0; nf < 4; ++nf) {
            const int m = row0 + mf * 16 + (lane >> 2);
            const int n = col0 + nf * 8 + (lane & 3) * 2;
            float v[4] = {acc[mf][nf][0], acc[mf][nf][1], acc[mf][nf][2], acc[mf][nf][3]};
            if (p.bias) {
                const float bz0 = p.bias[n], bz1 = p.bias[n + 1];
                v[0] += bz0; v[1] += bz1; v[2] += bz0; v[3] += bz1;
            }
            if (p.relu) {
#pragma unroll
                for (int q = 0; q < 4; ++q) v[q] = fmaxf(v[q], 0.f);
            }
            if (p.splitOut) {
                // rows m and m+8, cols n and n+1
#pragma unroll
                for (int q = 0; q < 4; ++q) {
                    const int mm = m + (q >> 1) * 8;
                    const int nn = n + (q & 1);
                    const long off = (long)b * p.sC + (long)mm * p.ldC + nn;
                    bf16 hi = __float2bfloat16(v[q]);
                    p.Ch[off] = hi;
                    p.Cl[off] = __float2bfloat16(v[q] - __bfloat162float(hi));
                }
            } else {
#pragma unroll
                for (int q = 0; q < 4; ++q) {
                    const int mm = m + (q >> 1) * 8;
                    const int nn = n + (q & 1);
                    if (nn < p.Nlim)
                        p.Cf[(long)b * p.sC + (long)mm * p.ldC + nn] = v[q];
                }
            }
        }
    }
}

// ---------------------------------------------------------------------------
extern "C" void kernel_launch(void* const* d_in, const int* in_sizes, int n_in,
                              void* d_out, int out_size)
{
    const float* x4  = (const float*)d_in[0];
    const float* att = (const float*)d_in[1];
    const float* W1  = (const float*)d_in[2];
    const float* b1  = (const float*)d_in[3];
    const float* W2  = (const float*)d_in[4];
    const float* b2  = (const float*)d_in[5];
    float* out = (float*)d_out;

    void *pL, *pXh, *pXl, *pLh, *pLl, *pTh, *pTl, *phh, *phl, *pT2h, *pT2l;
    void *pW1h, *pW1l, *pW2h, *pW2l, *pb1p, *pb2p;
    cudaGetSymbolAddress(&pL, g_L);
    cudaGetSymbolAddress(&pXh, g_Xh);  cudaGetSymbolAddress(&pXl, g_Xl);
    cudaGetSymbolAddress(&pLh, g_Lh);  cudaGetSymbolAddress(&pLl, g_Ll);
    cudaGetSymbolAddress(&pTh, g_Th);  cudaGetSymbolAddress(&pTl, g_Tl);
    cudaGetSymbolAddress(&phh, g_hh);  cudaGetSymbolAddress(&phl, g_hl);
    cudaGetSymbolAddress(&pT2h, g_T2h); cudaGetSymbolAddress(&pT2l, g_T2l);
    cudaGetSymbolAddress(&pW1h, g_W1h); cudaGetSymbolAddress(&pW1l, g_W1l);
    cudaGetSymbolAddress(&pW2h, g_W2h); cudaGetSymbolAddress(&pW2l, g_W2l);
    cudaGetSymbolAddress(&pb1p, g_b1p); cudaGetSymbolAddress(&pb2p, g_b2p);

    float* L = (float*)pL;
    bf16 *Xh = (bf16*)pXh, *Xl = (bf16*)pXl;
    bf16 *Lh = (bf16*)pLh, *Ll = (bf16*)pLl;
    bf16 *Th = (bf16*)pTh, *Tl = (bf16*)pTl;
    bf16 *hh = (bf16*)phh, *hl = (bf16*)phl;
    bf16 *T2h = (bf16*)pT2h, *T2l = (bf16*)pT2l;
    bf16 *W1h = (bf16*)pW1h, *W1l = (bf16*)pW1l;
    bf16 *W2h = (bf16*)pW2h, *W2l = (bf16*)pW2l;
    float *b1p = (float*)pb1p, *b2p = (float*)pb2p;

    // 1) adjacency + normalization (fp32)
    adj_kernel<<<dim3(8, 8, BB), 256>>>(x4, att, L);
    norm_kernel<<<dim3(BB * NN), 256>>>(L);

    // 2) splits
    {   // L -> Lh, Ll  [512][512]
        long tot = (long)NN * NN;
        split_kernel<<<dim3((unsigned)((tot + 255) / 256), BB), 256>>>(
            L, Lh, Ll, NN, NN, NN, tot, (long)NN * NN, (long)NN * NN);
    }
    {   // X -> Xh, Xl  [512][640]
        long tot = (long)NN * FFP;
        split_kernel<<<dim3((unsigned)((tot + 255) / 256), BB), 256>>>(
            x4, Xh, Xl, NN, FF, FFP, tot, (long)NN * FF, (long)NN * FFP);
    }
    {   // W1 -> [2][640][1024]
        long tot = (long)FFP * FHPN;
        split_kernel<<<dim3((unsigned)((tot + 255) / 256), 2), 256>>>(
            W1, W1h, W1l, FF, FH, FHPN, tot, (long)FF * FH, (long)FFP * FHPN);
    }
    {   // W2 -> [2][944][640]
        long tot = (long)FHPK * FFP;
        split_kernel<<<dim3((unsigned)((tot + 255) / 256), 2), 256>>>(
            W2, W2h, W2l, FH, FF, FFP, tot, (long)FH * FF, (long)FHPK * FFP);
    }
    biaspad_kernel<<<dim3((FHPN + 255) / 256), 256>>>(b1, b2);

    // 3) bmm1: T = L @ X  -> split (Th, Tl)
    {
        GP p = {};
        p.A[0] = Lh; p.B[0] = Xh; p.K[0] = NN;
        p.A[1] = Lh; p.B[1] = Xl; p.K[1] = NN;
        p.A[2] = Ll; p.B[2] = Xh; p.K[2] = NN;
        for (int i = 0; i < 3; ++i) { p.sA[i] = (long)NN * NN; p.sB[i] = (long)NN * FFP; }
        p.nseg = 3; p.ldA = NN; p.ldB = FFP;
        p.Ch = Th; p.Cl = Tl; p.sC = (long)NN * FFP; p.ldC = FFP;
        p.bias = nullptr; p.relu = 0; p.Nlim = FFP; p.splitOut = 1;
        mma_gemm<<<dim3(FFP / 128, NN / 128, BB), 256>>>(p);
    }

    // 4) layer1: h = relu([X|T] @ [W1_0;W1_1] + b1) -> split (hh, hl)
    {
        GP p = {};
        const bf16* W10h = W1h;                    const bf16* W10l = W1l;
        const bf16* W11h = W1h + (size_t)FFP * FHPN; const bf16* W11l = W1l + (size_t)FFP * FHPN;
        p.A[0] = Xh; p.B[0] = W10h; p.A[1] = Xh; p.B[1] = W10l; p.A[2] = Xl; p.B[2] = W10h;
        p.A[3] = Th; p.B[3] = W11h; p.A[4] = Th; p.B[4] = W11l; p.A[5] = Tl; p.B[5] = W11h;
        for (int i = 0; i < 6; ++i) { p.sA[i] = (long)NN * FFP; p.sB[i] = 0; p.K[i] = FFP; }
        p.nseg = 6; p.ldA = FFP; p.ldB = FHPN;
        p.Ch = hh; p.Cl = hl; p.sC = (long)NN * FHPN; p.ldC = FHPN;
        p.bias = b1p; p.relu = 1; p.Nlim = FHPN; p.splitOut = 1;
        mma_gemm<<<dim3(FHPN / 128, NN / 128, BB), 256>>>(p);
    }

    // 5) bmm2: T2 = L @ h -> split (T2h, T2l)
    {
        GP p = {};
        p.A[0] = Lh; p.B[0] = hh; p.K[0] = NN;
        p.A[1] = Lh; p.B[1] = hl; p.K[1] = NN;
        p.A[2] = Ll; p.B[2] = hh; p.K[2] = NN;
        for (int i = 0; i < 3; ++i) { p.sA[i] = (long)NN * NN; p.sB[i] = (long)NN * FHPN; }
        p.nseg = 3; p.ldA = NN; p.ldB = FHPN;
        p.Ch = T2h; p.Cl = T2l; p.sC = (long)NN * FHPN; p.ldC = FHPN;
        p.bias = nullptr; p.relu = 0; p.Nlim = FHPN; p.splitOut = 1;
        mma_gemm<<<dim3(FHPN / 128, NN / 128, BB), 256>>>(p);
    }

    // 6) layer2: out = relu([h|T2] @ [W2_0;W2_1] + b2) -> fp32 d_out
    {
        GP p = {};
        const bf16* W20h = W2h;                     const bf16* W20l = W2l;
        const bf16* W21h = W2h + (size_t)FHPK * FFP;  const bf16* W21l = W2l + (size_t)FHPK * FFP;
        p.A[0] = hh;  p.B[0] = W20h; p.A[1] = hh;  p.B[1] = W20l; p.A[2] = hl;  p.B[2] = W20h;
        p.A[3] = T2h; p.B[3] = W21h; p.A[4] = T2h; p.B[4] = W21l; p.A[5] = T2l; p.B[5] = W21h;
        for (int i = 0; i < 6; ++i) { p.sA[i] = (long)NN * FHPN; p.sB[i] = 0; p.K[i] = FHPK; }
        p.nseg = 6; p.ldA = FHPN; p.ldB = FFP;
        p.Cf = out; p.sC = (long)NN * FF; p.ldC = FF;
        p.bias = b2p; p.relu = 1; p.Nlim = FF; p.splitOut = 0;
        mma_gemm<<<dim3(FFP / 128, NN / 128, BB), 256>>>(p);
    }
}

// round 4
// speedup vs baseline: 2.0545x; 1.1276x over previous
#include <cuda_runtime.h>
#include <cuda_bf16.h>
#include <cstdint>

#define BB 16
#define NN 512
#define FF 625
#define FH 937
#define FFP 640      // F padded (mult of 128)
#define FHPN 1024    // Fh padded for N-dim (mult of 128)
#define FHPK 944     // Fh padded for K-dim (mult of 16)

typedef __nv_bfloat16 bf16;

// ---------------- scratch (no allocs allowed -> device globals) -------------
__device__ bf16  g_A[(size_t)BB * NN * NN];           // adjacency 0/1 (bf16, exact)
__device__ float g_dinv[(size_t)BB * NN];             // 1/deg per row

__device__ bf16 g_Xh[(size_t)BB * NN * FFP],  g_Xl[(size_t)BB * NN * FFP];
__device__ bf16 g_Th[(size_t)BB * NN * FFP],  g_Tl[(size_t)BB * NN * FFP];
__device__ bf16 g_hh[(size_t)BB * NN * FHPN], g_hl[(size_t)BB * NN * FHPN];
__device__ bf16 g_T2h[(size_t)BB * NN * FHPN], g_T2l[(size_t)BB * NN * FHPN];
__device__ bf16 g_W1h[2ul * FFP * FHPN],  g_W1l[2ul * FFP * FHPN];
__device__ bf16 g_W2h[2ul * FHPK * FFP],  g_W2l[2ul * FHPK * FFP];
__device__ float g_b1p[FHPN], g_b2p[FFP];

// ---------------------------------------------------------------------------
// Kernel 1: thresholded adjacency -> bf16 0/1 (values exact in bf16).
// ---------------------------------------------------------------------------
__global__ __launch_bounds__(256) void adj_kernel(
    const float* __restrict__ X, const float* __restrict__ att,
    bf16* __restrict__ A)
{
    __shared__ float sXi[32][68];
    __shared__ float sXj[32][68];

    const int b  = blockIdx.z;
    const int i0 = blockIdx.y * 64;
    const int j0 = blockIdx.x * 64;
    const float* Xb = X + (size_t)b * NN * FF;

    const int tid = threadIdx.x;
    const int tx = tid & 15;
    const int ty = tid >> 4;

    float acc[4][4];
#pragma unroll
    for (int r = 0; r < 4; ++r)
#pragma unroll
        for (int c = 0; c < 4; ++c) acc[r][c] = 0.f;

    const int lk = tid & 31;
    const int lr = tid >> 5;

    for (int k0 = 0; k0 < FF; k0 += 32) {
#pragma unroll
        for (int r = 0; r < 8; ++r) {
            const int row = lr + r * 8;
            const int k = k0 + lk;
            float vi = 0.f, vj = 0.f;
            if (k < FF) {
                vi = Xb[(size_t)(i0 + row) * FF + k];
                vj = Xb[(size_t)(j0 + row) * FF + k];
            }
            sXi[lk][row] = vi;
            sXj[lk][row] = vj;
        }
        __syncthreads();
#pragma unroll
        for (int kk = 0; kk < 32; ++kk) {
            const float4 av = *(const float4*)&sXi[kk][ty * 4];
            const float4 bv = *(const float4*)&sXj[kk][tx * 4];
            const float a_[4] = {av.x, av.y, av.z, av.w};
            const float b_[4] = {bv.x, bv.y, bv.z, bv.w};
#pragma unroll
            for (int r = 0; r < 4; ++r)
#pragma unroll
                for (int c = 0; c < 4; ++c)
                    acc[r][c] += fabsf(a_[r] - b_[c]);
        }
        __syncthreads();
    }

    const float* attb = att + b * NN;
    float ai[4], aj[4];
#pragma unroll
    for (int r = 0; r < 4; ++r) ai[r] = attb[i0 + ty * 4 + r];
#pragma unroll
    for (int c = 0; c < 4; ++c) aj[c] = attb[j0 + tx * 4 + c];

    bf16* Ab = A + (size_t)b * NN * NN;
#pragma unroll
    for (int r = 0; r < 4; ++r) {
        const int i = i0 + ty * 4 + r;
#pragma unroll
        for (int c = 0; c < 4; ++c) {
            const int j = j0 + tx * 4 + c;
            const bool keep =
                (acc[r][c] <= 180.0f && fabsf(ai[r] - aj[c]) <= 0.05f);
            Ab[(size_t)i * NN + j] = __float2bfloat16(keep ? 1.f : 0.f);
        }
    }
}

// ---------------------------------------------------------------------------
// Kernel 2: dinv[row] = 1 / rowsum(A). One block (256 thr) per row.
// ---------------------------------------------------------------------------
__global__ __launch_bounds__(256) void dinv_kernel(
    const bf16* __restrict__ A, float* __restrict__ dinv)
{
    const size_t row = blockIdx.x;
    const bf16* p = A + row * NN;
    const int t = threadIdx.x;

    float v = __bfloat162float(p[t]) + __bfloat162float(p[t + 256]);
#pragma unroll
    for (int o = 16; o; o >>= 1) v += __shfl_down_sync(0xffffffffu, v, o);

    __shared__ float swarp[8];
    if ((t & 31) == 0) swarp[t >> 5] = v;
    __syncthreads();
    if (t == 0) {
        float d = 0.f;
#pragma unroll
        for (int w = 0; w < 8; ++w) d += swarp[w];
        dinv[row] = 1.0f / d;   // deg >= 1 (diagonal)
    }
}

// ---------------------------------------------------------------------------
// Split fp32 -> (hi, lo) bf16 pair into zero-padded buffers.
// ---------------------------------------------------------------------------
__global__ __launch_bounds__(256) void split_kernel(
    const float* __restrict__ src, bf16* __restrict__ dh, bf16* __restrict__ dl,
    int R, int C, int Cp, long totalP, long sStride, long dStride)
{
    long idx = (long)blockIdx.x * 256 + threadIdx.x;
    if (idx >= totalP) return;
    const int b = blockIdx.y;
    const int r = (int)(idx / Cp);
    const int c = (int)(idx % Cp);
    float v = (r < R && c < C) ? src[(long)b * sStride + (long)r * C + c] : 0.f;
    bf16 hi = __float2bfloat16(v);
    float lo = v - __bfloat162float(hi);
    dh[(long)b * dStride + idx] = hi;
    dl[(long)b * dStride + idx] = __float2bfloat16(lo);
}

__global__ void biaspad_kernel(const float* __restrict__ b1, const float* __restrict__ b2)
{
    int t = blockIdx.x * 256 + threadIdx.x;
    if (t < FHPN) g_b1p[t] = (t < FH) ? b1[t] : 0.f;
    if (t < FFP)  g_b2p[t] = (t < FF) ? b2[t] : 0.f;
}

// ---------------------------------------------------------------------------
// Tensor-core GEMM v2: 4-stage cp.async pipeline, one barrier per K16 step.
// C[b] = op( rowScale ⊙ (sum_seg A_seg[b] @ B_seg[b]) + bias )
// Block tile 128x128, 8 warps (warp tile 64x32), bf16 mma.sync.m16n8k16.
// All segments share the same K (p.steps = K/16).
// ---------------------------------------------------------------------------
struct GP {
    const bf16* A[6];
    const bf16* B[6];
    long sA[6], sB[6];
    int  nseg, steps;
    int  ldA, ldB;
    float* Cf; bf16* Ch; bf16* Cl;
    long sC; int ldC;
    const float* bias;
    const float* rowScale;   // per-row scale (stride NN per batch), may be null
    int relu, Nlim, splitOut;
};

__device__ __forceinline__ void cp16(uint32_t dst, const void* src) {
    asm volatile("cp.async.cg.shared.global [%0], [%1], 16;\n" :: "r"(dst), "l"(src));
}
__device__ __forceinline__ void ldsm4(uint32_t* r, uint32_t addr) {
    asm volatile("ldmatrix.sync.aligned.m8n8.x4.shared.b16 {%0,%1,%2,%3}, [%4];\n"
                 : "=r"(r[0]), "=r"(r[1]), "=r"(r[2]), "=r"(r[3]) : "r"(addr));
}
__device__ __forceinline__ void ldsm4t(uint32_t* r, uint32_t addr) {
    asm volatile("ldmatrix.sync.aligned.m8n8.x4.trans.shared.b16 {%0,%1,%2,%3}, [%4];\n"
                 : "=r"(r[0]), "=r"(r[1]), "=r"(r[2]), "=r"(r[3]) : "r"(addr));
}
__device__ __forceinline__ void mma16816(float* d, const uint32_t* a, uint32_t b0, uint32_t b1) {
    asm volatile(
        "mma.sync.aligned.m16n8k16.row.col.f32.bf16.bf16.f32 "
        "{%0,%1,%2,%3}, {%4,%5,%6,%7}, {%8,%9}, {%0,%1,%2,%3};\n"
        : "+f"(d[0]), "+f"(d[1]), "+f"(d[2]), "+f"(d[3])
        : "r"(a[0]), "r"(a[1]), "r"(a[2]), "r"(a[3]), "r"(b0), "r"(b1));
}

__global__ __launch_bounds__(256, 2) void mma_gemm(GP p)
{
    // 4 stages x (A 128x16 bf16 = 4KB, B 16x128 bf16 = 4KB) = 32KB
    __shared__ __align__(128) char smem[32768];
    const uint32_t sbase = (uint32_t)__cvta_generic_to_shared(smem);

    const int tid  = threadIdx.x;
    const int lane = tid & 31;
    const int warp = tid >> 5;
    const int b  = blockIdx.z;
    const int m0 = blockIdx.y * 128;
    const int n0 = blockIdx.x * 128;
    const int wm = (warp & 1) * 64;
    const int wn = (warp >> 1) * 32;

    float acc[4][4][4];
#pragma unroll
    for (int i = 0; i < 4; ++i)
#pragma unroll
        for (int j = 0; j < 4; ++j)
#pragma unroll
            for (int k = 0; k < 4; ++k) acc[i][j][k] = 0.f;

    // producer indices (one 16B chunk each for A and B per thread)
    const int ar = tid >> 1, ac = tid & 1;     // A: 128 rows x 2 chunks
    const int bk = tid >> 4, bc = tid & 15;    // B: 16 rows x 16 chunks
    const uint32_t aDst = (uint32_t)((ar * 2 + (ac ^ ((ar >> 2) & 1))) * 16);
    const uint32_t bDst = (uint32_t)(4096 + (bk * 16 + (bc ^ (bk & 7))) * 16);

    // consumer (ldmatrix) byte offsets within a stage
    uint32_t aLd[4], bLd[2];
#pragma unroll
    for (int f = 0; f < 4; ++f) {
        const int r = wm + f * 16 + (lane & 15);
        const int c = (lane >> 4) & 1;
        aLd[f] = (uint32_t)((r * 2 + (c ^ ((r >> 2) & 1))) * 16);
    }
#pragma unroll
    for (int g = 0; g < 2; ++g) {
        const int k = lane & 15;
        const int cn = (wn >> 3) + g * 2 + ((lane >> 4) & 1);
        bLd[g] = (uint32_t)(4096 + (k * 16 + (cn ^ (k & 7))) * 16);
    }

    const int steps = p.steps;
    const int total = p.nseg * steps;

    const long aOff = (long)(m0 + ar) * p.ldA + ac * 8;
    const long bOff = (long)bk * p.ldB + n0 + bc * 8;
    const bf16* Ag = p.A[0] + (long)b * p.sA[0] + aOff;
    const bf16* Bg = p.B[0] + (long)b * p.sB[0] + bOff;
    int pSeg = 0, pKs = 0;

    auto issue = [&](int stage) {
        cp16(sbase + (uint32_t)stage * 8192 + aDst, Ag + (long)pKs * 16);
        cp16(sbase + (uint32_t)stage * 8192 + bDst, Bg + (long)pKs * 16 * p.ldB);
        if (++pKs == steps) {
            pKs = 0;
            if (++pSeg < p.nseg) {
                Ag = p.A[pSeg] + (long)b * p.sA[pSeg] + aOff;
                Bg = p.B[pSeg] + (long)b * p.sB[pSeg] + bOff;
            }
        }
    };

#pragma unroll
    for (int i = 0; i < 3; ++i) {          // total >= 64 always
        issue(i);
        asm volatile("cp.async.commit_group;\n");
    }

    for (int s = 0; s < total; ++s) {
        asm volatile("cp.async.wait_group 2;\n");
        __syncthreads();

        const uint32_t so = (uint32_t)((s & 3) * 8192);
        uint32_t afr[4][4], bfr[2][4];
#pragma unroll
        for (int f = 0; f < 4; ++f) ldsm4(afr[f], sbase + so + aLd[f]);
#pragma unroll
        for (int g = 0; g < 2; ++g) ldsm4t(bfr[g], sbase + so + bLd[g]);

        if (s + 3 < total) issue((s + 3) & 3);
        asm volatile("cp.async.commit_group;\n");

#pragma unroll
        for (int mf = 0; mf < 4; ++mf)
#pragma unroll
            for (int nf = 0; nf < 4; ++nf) {
                const uint32_t* bb = bfr[nf >> 1];
                const int sub = (nf & 1) * 2;
                mma16816(acc[mf][nf], afr[mf], bb[sub], bb[sub + 1]);
            }
    }

    // -------- epilogue --------
    const float* rsB = p.rowScale ? (p.rowScale + (long)b * NN) : nullptr;
    const int row0 = m0 + wm;
    const int col0 = n0 + wn;
#pragma unroll
    for (int mf = 0; mf < 4; ++mf) {
        const int m = row0 + mf * 16 + (lane >> 2);
        const float rs0 = rsB ? rsB[m] : 1.f;
        const float rs1 = rsB ? rsB[m + 8] : 1.f;
#pragma unroll
        for (int nf = 0; nf < 4; ++nf) {
            const int n = col0 + nf * 8 + (lane & 3) * 2;
            float v[4] = {acc[mf][nf][0] * rs0, acc[mf][nf][1] * rs0,
                          acc[mf][nf][2] * rs1, acc[mf][nf][3] * rs1};
            if (p.bias) {
                const float bz0 = p.bias[n], bz1 = p.bias[n + 1];
                v[0] += bz0; v[1] += bz1; v[2] += bz0; v[3] += bz1;
            }
            if (p.relu) {
#pragma unroll
                for (int q = 0; q < 4; ++q) v[q] = fmaxf(v[q], 0.f);
            }
            if (p.splitOut) {
#pragma unroll
                for (int q = 0; q < 4; ++q) {
                    const int mm = m + (q >> 1) * 8;
                    const int nn = n + (q & 1);
                    const long off = (long)b * p.sC + (long)mm * p.ldC + nn;
                    bf16 hi = __float2bfloat16(v[q]);
                    p.Ch[off] = hi;
                    p.Cl[off] = __float2bfloat16(v[q] - __bfloat162float(hi));
                }
            } else {
#pragma unroll
                for (int q = 0; q < 4; ++q) {
                    const int mm = m + (q >> 1) * 8;
                    const int nn = n + (q & 1);
                    if (nn < p.Nlim)
                        p.Cf[(long)b * p.sC + (long)mm * p.ldC + nn] = v[q];
                }
            }
        }
    }
}

// ---------------------------------------------------------------------------
extern "C" void kernel_launch(void* const* d_in, const int* in_sizes, int n_in,
                              void* d_out, int out_size)
{
    const float* x4  = (const float*)d_in[0];
    const float* att = (const float*)d_in[1];
    const float* W1  = (const float*)d_in[2];
    const float* b1  = (const float*)d_in[3];
    const float* W2  = (const float*)d_in[4];
    const float* b2  = (const float*)d_in[5];
    float* out = (float*)d_out;

    void *pA, *pDinv, *pXh, *pXl, *pTh, *pTl, *phh, *phl, *pT2h, *pT2l;
    void *pW1h, *pW1l, *pW2h, *pW2l, *pb1p, *pb2p;
    cudaGetSymbolAddress(&pA, g_A);
    cudaGetSymbolAddress(&pDinv, g_dinv);
    cudaGetSymbolAddress(&pXh, g_Xh);  cudaGetSymbolAddress(&pXl, g_Xl);
    cudaGetSymbolAddress(&pTh, g_Th);  cudaGetSymbolAddress(&pTl, g_Tl);
    cudaGetSymbolAddress(&phh, g_hh);  cudaGetSymbolAddress(&phl, g_hl);
    cudaGetSymbolAddress(&pT2h, g_T2h); cudaGetSymbolAddress(&pT2l, g_T2l);
    cudaGetSymbolAddress(&pW1h, g_W1h); cudaGetSymbolAddress(&pW1l, g_W1l);
    cudaGetSymbolAddress(&pW2h, g_W2h); cudaGetSymbolAddress(&pW2l, g_W2l);
    cudaGetSymbolAddress(&pb1p, g_b1p); cudaGetSymbolAddress(&pb2p, g_b2p);

    bf16 *Ab = (bf16*)pA;
    float *dinv = (float*)pDinv;
    bf16 *Xh = (bf16*)pXh, *Xl = (bf16*)pXl;
    bf16 *Th = (bf16*)pTh, *Tl = (bf16*)pTl;
    bf16 *hh = (bf16*)phh, *hl = (bf16*)phl;
    bf16 *T2h = (bf16*)pT2h, *T2l = (bf16*)pT2l;
    bf16 *W1h = (bf16*)pW1h, *W1l = (bf16*)pW1l;
    bf16 *W2h = (bf16*)pW2h, *W2l = (bf16*)pW2l;
    float *b1p = (float*)pb1p, *b2p = (float*)pb2p;

    // 1) adjacency (bf16 0/1) + degrees
    adj_kernel<<<dim3(8, 8, BB), 256>>>(x4, att, Ab);
    dinv_kernel<<<dim3(BB * NN), 256>>>(Ab, dinv);

    // 2) splits (X, W1, W2) + bias pad
    {   // X -> Xh, Xl  [512][640]
        long tot = (long)NN * FFP;
        split_kernel<<<dim3((unsigned)((tot + 255) / 256), BB), 256>>>(
            x4, Xh, Xl, NN, FF, FFP, tot, (long)NN * FF, (long)NN * FFP);
    }
    {   // W1 -> [2][640][1024]
        long tot = (long)FFP * FHPN;
        split_kernel<<<dim3((unsigned)((tot + 255) / 256), 2), 256>>>(
            W1, W1h, W1l, FF, FH, FHPN, tot, (long)FF * FH, (long)FFP * FHPN);
    }
    {   // W2 -> [2][944][640]
        long tot = (long)FHPK * FFP;
        split_kernel<<<dim3((unsigned)((tot + 255) / 256), 2), 256>>>(
            W2, W2h, W2l, FH, FF, FFP, tot, (long)FH * FF, (long)FHPK * FFP);
    }
    biaspad_kernel<<<dim3((FHPN + 255) / 256), 256>>>(b1, b2);

    // 3) bmm1: T = dinv ⊙ (A@Xh + A@Xl) -> split (Th, Tl)
    {
        GP p = {};
        p.A[0] = Ab; p.B[0] = Xh;
        p.A[1] = Ab; p.B[1] = Xl;
        for (int i = 0; i < 2; ++i) { p.sA[i] = (long)NN * NN; p.sB[i] = (long)NN * FFP; }
        p.nseg = 2; p.steps = NN / 16; p.ldA = NN; p.ldB = FFP;
        p.Ch = Th; p.Cl = Tl; p.sC = (long)NN * FFP; p.ldC = FFP;
        p.rowScale = dinv;
        p.bias = nullptr; p.relu = 0; p.Nlim = FFP; p.splitOut = 1;
        mma_gemm<<<dim3(FFP / 128, NN / 128, BB), 256>>>(p);
    }

    // 4) layer1: h = relu([X|T] @ [W1_0;W1_1] + b1) -> split (hh, hl)
    {
        GP p = {};
        const bf16* W10h = W1h;                      const bf16* W10l = W1l;
        const bf16* W11h = W1h + (size_t)FFP * FHPN; const bf16* W11l = W1l + (size_t)FFP * FHPN;
        p.A[0] = Xh; p.B[0] = W10h; p.A[1] = Xh; p.B[1] = W10l; p.A[2] = Xl; p.B[2] = W10h;
        p.A[3] = Th; p.B[3] = W11h; p.A[4] = Th; p.B[4] = W11l; p.A[5] = Tl; p.B[5] = W11h;
        for (int i = 0; i < 6; ++i) { p.sA[i] = (long)NN * FFP; p.sB[i] = 0; }
        p.nseg = 6; p.steps = FFP / 16; p.ldA = FFP; p.ldB = FHPN;
        p.Ch = hh; p.Cl = hl; p.sC = (long)NN * FHPN; p.ldC = FHPN;
        p.rowScale = nullptr;
        p.bias = b1p; p.relu = 1; p.Nlim = FHPN; p.splitOut = 1;
        mma_gemm<<<dim3(FHPN / 128, NN / 128, BB), 256>>>(p);
    }

    // 5) bmm2: T2 = dinv ⊙ (A@hh + A@hl) -> split (T2h, T2l)
    {
        GP p = {};
        p.A[0] = Ab; p.B[0] = hh;
        p.A[1] = Ab; p.B[1] = hl;
        for (int i = 0; i < 2; ++i) { p.sA[i] = (long)NN * NN; p.sB[i] = (long)NN * FHPN; }
        p.nseg = 2; p.steps = NN / 16; p.ldA = NN; p.ldB = FHPN;
        p.Ch = T2h; p.Cl = T2l; p.sC = (long)NN * FHPN; p.ldC = FHPN;
        p.rowScale = dinv;
        p.bias = nullptr; p.relu = 0; p.Nlim = FHPN; p.splitOut = 1;
        mma_gemm<<<dim3(FHPN / 128, NN / 128, BB), 256>>>(p);
    }

    // 6) layer2: out = relu([h|T2] @ [W2_0;W2_1] + b2) -> fp32 d_out
    {
        GP p = {};
        const bf16* W20h = W2h;                      const bf16* W20l = W2l;
        const bf16* W21h = W2h + (size_t)FHPK * FFP; const bf16* W21l = W2l + (size_t)FHPK * FFP;
        p.A[0] = hh;  p.B[0] = W20h; p.A[1] = hh;  p.B[1] = W20l; p.A[2] = hl;  p.B[2] = W20h;
        p.A[3] = T2h; p.B[3] = W21h; p.A[4] = T2h; p.B[4] = W21l; p.A[5] = T2l; p.B[5] = W21h;
        for (int i = 0; i < 6; ++i) { p.sA[i] = (long)NN * FHPN; p.sB[i] = 0; }
        p.nseg = 6; p.steps = FHPK / 16; p.ldA = FHPN; p.ldB = FFP;
        p.Cf = out; p.sC = (long)NN * FF; p.ldC = FF;
        p.rowScale = nullptr;
        p.bias = b2p; p.relu = 1; p.Nlim = FF; p.splitOut = 0;
        mma_gemm<<<dim3(FFP / 128, NN / 128, BB), 256>>>(p);
    }
}

// round 5
// speedup vs baseline: 2.1094x; 1.0267x over previous
#include <cuda_runtime.h>
#include <cuda_bf16.h>
#include <cstdint>

#define BB 16
#define NN 512
#define FF 625
#define FH 937
#define FFP 640      // F padded (mult of 128)
#define FHPN 1024    // Fh padded for N-dim (mult of 128)
#define FHPK 944     // Fh padded for K-dim (mult of 16)

typedef __nv_bfloat16 bf16;

// ---------------- scratch (no allocs allowed -> device globals) -------------
__device__ bf16  g_A[(size_t)BB * NN * NN];   // adjacency 0/1 in SORTED space
__device__ float g_dinv[(size_t)BB * NN];     // 1/deg per sorted row
__device__ float g_atts[(size_t)BB * NN];     // sorted att values
__device__ int   g_perm[(size_t)BB * NN];     // perm[i] = original index of i-th smallest

__device__ bf16 g_Xh[(size_t)BB * NN * FFP],  g_Xl[(size_t)BB * NN * FFP];
__device__ bf16 g_Th[(size_t)BB * NN * FFP],  g_Tl[(size_t)BB * NN * FFP];
__device__ bf16 g_hh[(size_t)BB * NN * FHPN], g_hl[(size_t)BB * NN * FHPN];
__device__ bf16 g_T2h[(size_t)BB * NN * FHPN], g_T2l[(size_t)BB * NN * FHPN];
__device__ bf16 g_W1h[2ul * FFP * FHPN],  g_W1l[2ul * FFP * FHPN];
__device__ bf16 g_W2h[2ul * FHPK * FFP],  g_W2l[2ul * FHPK * FFP];
__device__ float g_b1p[FHPN], g_b2p[FFP];

// ---------------------------------------------------------------------------
// Kernel 0: bitonic sort of att per batch -> (sorted values, permutation).
// ---------------------------------------------------------------------------
__global__ __launch_bounds__(512) void sort_kernel(const float* __restrict__ att)
{
    __shared__ float key[NN];
    __shared__ int   idx[NN];
    const int b = blockIdx.x;
    const int t = threadIdx.x;

    key[t] = att[(size_t)b * NN + t];
    idx[t] = t;
    __syncthreads();

    for (int sz = 2; sz <= NN; sz <<= 1) {
        for (int st = sz >> 1; st > 0; st >>= 1) {
            const int p = t ^ st;
            if (p > t) {
                const bool up = ((t & sz) == 0);
                const float a = key[t], c = key[p];
                if (up ? (a > c) : (a < c)) {
                    key[t] = c; key[p] = a;
                    const int ia = idx[t]; idx[t] = idx[p]; idx[p] = ia;
                }
            }
            __syncthreads();
        }
    }
    g_atts[(size_t)b * NN + t] = key[t];
    g_perm[(size_t)b * NN + t] = idx[t];
}

// ---------------------------------------------------------------------------
// Kernel 1: thresholded adjacency in sorted space, with att-band pruning.
// Pruned tiles (no att overlap possible) just write zeros and exit.
// ---------------------------------------------------------------------------
__global__ __launch_bounds__(256) void adj_kernel(
    const float* __restrict__ X, bf16* __restrict__ A)
{
    const int b  = blockIdx.z;
    const int i0 = blockIdx.y * 64;
    const int j0 = blockIdx.x * 64;
    const float* as = g_atts + (size_t)b * NN;
    const int* permB = g_perm + (size_t)b * NN;
    bf16* Ab = A + (size_t)b * NN * NN;
    const int tid = threadIdx.x;

    // ---- prune: sorted att -> valid j's contiguous; conservative epsilon ----
    if (as[j0] > as[i0 + 63] + 0.0501f || as[j0 + 63] < as[i0] - 0.0501f) {
        const int r = tid >> 2, c4 = tid & 3;      // 4 threads per row, 2 x 16B each
        float4 z = make_float4(0.f, 0.f, 0.f, 0.f);
        float4* row = (float4*)(Ab + (size_t)(i0 + r) * NN + j0);
        row[c4 * 2] = z;
        row[c4 * 2 + 1] = z;
        return;
    }

    __shared__ float sXi[32][68];
    __shared__ float sXj[32][68];

    const float* Xb = X + (size_t)b * NN * FF;
    const int tx = tid & 15;
    const int ty = tid >> 4;

    float acc[4][4];
#pragma unroll
    for (int r = 0; r < 4; ++r)
#pragma unroll
        for (int c = 0; c < 4; ++c) acc[r][c] = 0.f;

    const int lk = tid & 31;
    const int lr = tid >> 5;

    int piR[8], pjR[8];
#pragma unroll
    for (int r = 0; r < 8; ++r) {
        piR[r] = permB[i0 + lr + r * 8];
        pjR[r] = permB[j0 + lr + r * 8];
    }

    for (int k0 = 0; k0 < FF; k0 += 32) {
#pragma unroll
        for (int r = 0; r < 8; ++r) {
            const int row = lr + r * 8;
            const int k = k0 + lk;
            float vi = 0.f, vj = 0.f;
            if (k < FF) {
                vi = Xb[(size_t)piR[r] * FF + k];
                vj = Xb[(size_t)pjR[r] * FF + k];
            }
            sXi[lk][row] = vi;
            sXj[lk][row] = vj;
        }
        __syncthreads();
#pragma unroll
        for (int kk = 0; kk < 32; ++kk) {
            const float4 av = *(const float4*)&sXi[kk][ty * 4];
            const float4 bv = *(const float4*)&sXj[kk][tx * 4];
            const float a_[4] = {av.x, av.y, av.z, av.w};
            const float b_[4] = {bv.x, bv.y, bv.z, bv.w};
#pragma unroll
            for (int r = 0; r < 4; ++r)
#pragma unroll
                for (int c = 0; c < 4; ++c)
                    acc[r][c] += fabsf(a_[r] - b_[c]);
        }
        __syncthreads();
    }

    float ai[4], aj[4];
#pragma unroll
    for (int r = 0; r < 4; ++r) ai[r] = as[i0 + ty * 4 + r];
#pragma unroll
    for (int c = 0; c < 4; ++c) aj[c] = as[j0 + tx * 4 + c];

#pragma unroll
    for (int r = 0; r < 4; ++r) {
        const int i = i0 + ty * 4 + r;
#pragma unroll
        for (int c = 0; c < 4; ++c) {
            const int j = j0 + tx * 4 + c;
            const bool keep =
                (acc[r][c] <= 180.0f && fabsf(ai[r] - aj[c]) <= 0.05f);
            Ab[(size_t)i * NN + j] = __float2bfloat16(keep ? 1.f : 0.f);
        }
    }
}

// ---------------------------------------------------------------------------
// Kernel 2: dinv[row] = 1 / rowsum(A).
// ---------------------------------------------------------------------------
__global__ __launch_bounds__(256) void dinv_kernel(
    const bf16* __restrict__ A, float* __restrict__ dinv)
{
    const size_t row = blockIdx.x;
    const bf16* p = A + row * NN;
    const int t = threadIdx.x;

    float v = __bfloat162float(p[t]) + __bfloat162float(p[t + 256]);
#pragma unroll
    for (int o = 16; o; o >>= 1) v += __shfl_down_sync(0xffffffffu, v, o);

    __shared__ float swarp[8];
    if ((t & 31) == 0) swarp[t >> 5] = v;
    __syncthreads();
    if (t == 0) {
        float d = 0.f;
#pragma unroll
        for (int w = 0; w < 8; ++w) d += swarp[w];
        dinv[row] = 1.0f / d;
    }
}

// ---------------------------------------------------------------------------
// Split fp32 -> (hi, lo) bf16, zero-padded; optional row gather via perm.
// ---------------------------------------------------------------------------
__global__ __launch_bounds__(256) void split_kernel(
    const float* __restrict__ src, bf16* __restrict__ dh, bf16* __restrict__ dl,
    int R, int C, int Cp, long totalP, long sStride, long dStride,
    const int* __restrict__ perm)
{
    long idx = (long)blockIdx.x * 256 + threadIdx.x;
    if (idx >= totalP) return;
    const int b = blockIdx.y;
    const int r = (int)(idx / Cp);
    const int c = (int)(idx % Cp);
    float v = 0.f;
    if (r < R && c < C) {
        const int sr = perm ? perm[(long)b * NN + r] : r;
        v = src[(long)b * sStride + (long)sr * C + c];
    }
    bf16 hi = __float2bfloat16(v);
    float lo = v - __bfloat162float(hi);
    dh[(long)b * dStride + idx] = hi;
    dl[(long)b * dStride + idx] = __float2bfloat16(lo);
}

__global__ void biaspad_kernel(const float* __restrict__ b1, const float* __restrict__ b2)
{
    int t = blockIdx.x * 256 + threadIdx.x;
    if (t < FHPN) g_b1p[t] = (t < FH) ? b1[t] : 0.f;
    if (t < FFP)  g_b2p[t] = (t < FF) ? b2[t] : 0.f;
}

// ---------------------------------------------------------------------------
// Tensor-core GEMM v3: 128x128 block, 4 warps (warp tile 64x64), 128 threads,
// 4-stage cp.async pipeline. C = op(rowScale ⊙ ΣA_seg@B_seg + bias),
// optional output row permutation on the fp32 path.
// ---------------------------------------------------------------------------
struct GP {
    const bf16* A[6];
    const bf16* B[6];
    long sA[6], sB[6];
    int  nseg, steps;
    int  ldA, ldB;
    float* Cf; bf16* Ch; bf16* Cl;
    long sC; int ldC;
    const float* bias;
    const float* rowScale;
    const int* outPerm;
    int relu, Nlim, splitOut;
};

__device__ __forceinline__ void cp16(uint32_t dst, const void* src) {
    asm volatile("cp.async.cg.shared.global [%0], [%1], 16;\n" :: "r"(dst), "l"(src));
}
__device__ __forceinline__ void ldsm4(uint32_t* r, uint32_t addr) {
    asm volatile("ldmatrix.sync.aligned.m8n8.x4.shared.b16 {%0,%1,%2,%3}, [%4];\n"
                 : "=r"(r[0]), "=r"(r[1]), "=r"(r[2]), "=r"(r[3]) : "r"(addr));
}
__device__ __forceinline__ void ldsm4t(uint32_t* r, uint32_t addr) {
    asm volatile("ldmatrix.sync.aligned.m8n8.x4.trans.shared.b16 {%0,%1,%2,%3}, [%4];\n"
                 : "=r"(r[0]), "=r"(r[1]), "=r"(r[2]), "=r"(r[3]) : "r"(addr));
}
__device__ __forceinline__ void mma16816(float* d, const uint32_t* a, uint32_t b0, uint32_t b1) {
    asm volatile(
        "mma.sync.aligned.m16n8k16.row.col.f32.bf16.bf16.f32 "
        "{%0,%1,%2,%3}, {%4,%5,%6,%7}, {%8,%9}, {%0,%1,%2,%3};\n"
        : "+f"(d[0]), "+f"(d[1]), "+f"(d[2]), "+f"(d[3])
        : "r"(a[0]), "r"(a[1]), "r"(a[2]), "r"(a[3]), "r"(b0), "r"(b1));
}

__global__ __launch_bounds__(128, 2) void mma_gemm(GP p)
{
    // 4 stages x (A 128x16 = 4KB, B 16x128 = 4KB) = 32KB
    __shared__ __align__(128) char smem[32768];
    const uint32_t sbase = (uint32_t)__cvta_generic_to_shared(smem);

    const int tid  = threadIdx.x;
    const int lane = tid & 31;
    const int warp = tid >> 5;
    const int b  = blockIdx.z;
    const int m0 = blockIdx.y * 128;
    const int n0 = blockIdx.x * 128;
    const int wm = (warp & 1) * 64;
    const int wn = (warp >> 1) * 64;

    float acc[4][8][4];
#pragma unroll
    for (int i = 0; i < 4; ++i)
#pragma unroll
        for (int j = 0; j < 8; ++j)
#pragma unroll
            for (int k = 0; k < 4; ++k) acc[i][j][k] = 0.f;

    // producers: each thread loads 2 A chunks (row tid, cols 0/8)
    // and 2 B chunks (rows bk/bk+8, chunk col bc)
    const int ar = tid;
    const int bk = tid >> 4;        // 0..7
    const int bc = tid & 15;
    const uint32_t aDst0 = (uint32_t)((ar * 2 + (0 ^ ((ar >> 2) & 1))) * 16);
    const uint32_t aDst1 = (uint32_t)((ar * 2 + (1 ^ ((ar >> 2) & 1))) * 16);
    const uint32_t bDst0 = (uint32_t)(4096 + (bk * 16 + (bc ^ (bk & 7))) * 16);
    const uint32_t bDst1 = bDst0 + 2048;   // row bk+8: (bk+8)&7 == bk&7

    // consumer (ldmatrix) byte offsets within a stage
    uint32_t aLd[4], bLd[4];
#pragma unroll
    for (int f = 0; f < 4; ++f) {
        const int r = wm + f * 16 + (lane & 15);
        const int c = (lane >> 4) & 1;
        aLd[f] = (uint32_t)((r * 2 + (c ^ ((r >> 2) & 1))) * 16);
    }
#pragma unroll
    for (int g = 0; g < 4; ++g) {
        const int kk = lane & 15;
        const int cn = (wn >> 3) + g * 2 + ((lane >> 4) & 1);
        bLd[g] = (uint32_t)(4096 + (kk * 16 + (cn ^ (kk & 7))) * 16);
    }

    const int steps = p.steps;
    const int total = p.nseg * steps;

    const long aOff = (long)(m0 + ar) * p.ldA;
    const long bOff = (long)bk * p.ldB + n0 + bc * 8;
    const bf16* Ag = p.A[0] + (long)b * p.sA[0] + aOff;
    const bf16* Bg = p.B[0] + (long)b * p.sB[0] + bOff;
    int pSeg = 0, pKs = 0;

    auto issue = [&](int stage) {
        const uint32_t base = sbase + (uint32_t)stage * 8192;
        const bf16* as_ = Ag + (long)pKs * 16;
        const bf16* bs_ = Bg + (long)pKs * 16 * p.ldB;
        cp16(base + aDst0, as_);
        cp16(base + aDst1, as_ + 8);
        cp16(base + bDst0, bs_);
        cp16(base + bDst1, bs_ + (long)8 * p.ldB);
        if (++pKs == steps) {
            pKs = 0;
            if (++pSeg < p.nseg) {
                Ag = p.A[pSeg] + (long)b * p.sA[pSeg] + aOff;
                Bg = p.B[pSeg] + (long)b * p.sB[pSeg] + bOff;
            }
        }
    };

#pragma unroll
    for (int i = 0; i < 3; ++i) {   // total >= 64 for all our launches
        issue(i);
        asm volatile("cp.async.commit_group;\n");
    }

    for (int s = 0; s < total; ++s) {
        asm volatile("cp.async.wait_group 2;\n");
        __syncthreads();

        const uint32_t so = (uint32_t)((s & 3) * 8192);
        uint32_t afr[4][4], bfr[4][4];
#pragma unroll
        for (int f = 0; f < 4; ++f) ldsm4(afr[f], sbase + so + aLd[f]);
#pragma unroll
        for (int g = 0; g < 4; ++g) ldsm4t(bfr[g], sbase + so + bLd[g]);

        if (s + 3 < total) issue((s + 3) & 3);
        asm volatile("cp.async.commit_group;\n");

#pragma unroll
        for (int mf = 0; mf < 4; ++mf)
#pragma unroll
            for (int nf = 0; nf < 8; ++nf) {
                const uint32_t* bb = bfr[nf >> 1];
                const int sub = (nf & 1) * 2;
                mma16816(acc[mf][nf], afr[mf], bb[sub], bb[sub + 1]);
            }
    }

    // -------- epilogue --------
    const float* rsB = p.rowScale ? (p.rowScale + (long)b * NN) : nullptr;
    const int* opB = p.outPerm ? (p.outPerm + (long)b * NN) : nullptr;
    const int row0 = m0 + wm;
    const int col0 = n0 + wn;
#pragma unroll
    for (int mf = 0; mf < 4; ++mf) {
        const int m = row0 + mf * 16 + (lane >> 2);
        const float rs0 = rsB ? rsB[m] : 1.f;
        const float rs1 = rsB ? rsB[m + 8] : 1.f;
#pragma unroll
        for (int nf = 0; nf < 8; ++nf) {
            const int n = col0 + nf * 8 + (lane & 3) * 2;
            float v[4] = {acc[mf][nf][0] * rs0, acc[mf][nf][1] * rs0,
                          acc[mf][nf][2] * rs1, acc[mf][nf][3] * rs1};
            if (p.bias) {
                const float bz0 = p.bias[n], bz1 = p.bias[n + 1];
                v[0] += bz0; v[1] += bz1; v[2] += bz0; v[3] += bz1;
            }
            if (p.relu) {
#pragma unroll
                for (int q = 0; q < 4; ++q) v[q] = fmaxf(v[q], 0.f);
            }
            if (p.splitOut) {
#pragma unroll
                for (int q = 0; q < 4; ++q) {
                    const int mm = m + (q >> 1) * 8;
                    const int nn = n + (q & 1);
                    const long off = (long)b * p.sC + (long)mm * p.ldC + nn;
                    bf16 hi = __float2bfloat16(v[q]);
                    p.Ch[off] = hi;
                    p.Cl[off] = __float2bfloat16(v[q] - __bfloat162float(hi));
                }
            } else {
#pragma unroll
                for (int q = 0; q < 4; ++q) {
                    const int mm = m + (q >> 1) * 8;
                    const int nn = n + (q & 1);
                    if (nn < p.Nlim) {
                        const int mo = opB ? opB[mm] : mm;
                        p.Cf[(long)b * p.sC + (long)mo * p.ldC + nn] = v[q];
                    }
                }
            }
        }
    }
}

// ---------------------------------------------------------------------------
extern "C" void kernel_launch(void* const* d_in, const int* in_sizes, int n_in,
                              void* d_out, int out_size)
{
    const float* x4  = (const float*)d_in[0];
    const float* att = (const float*)d_in[1];
    const float* W1  = (const float*)d_in[2];
    const float* b1  = (const float*)d_in[3];
    const float* W2  = (const float*)d_in[4];
    const float* b2  = (const float*)d_in[5];
    float* out = (float*)d_out;

    void *pA, *pDinv, *pPerm, *pXh, *pXl, *pTh, *pTl, *phh, *phl, *pT2h, *pT2l;
    void *pW1h, *pW1l, *pW2h, *pW2l, *pb1p, *pb2p;
    cudaGetSymbolAddress(&pA, g_A);
    cudaGetSymbolAddress(&pDinv, g_dinv);
    cudaGetSymbolAddress(&pPerm, g_perm);
    cudaGetSymbolAddress(&pXh, g_Xh);  cudaGetSymbolAddress(&pXl, g_Xl);
    cudaGetSymbolAddress(&pTh, g_Th);  cudaGetSymbolAddress(&pTl, g_Tl);
    cudaGetSymbolAddress(&phh, g_hh);  cudaGetSymbolAddress(&phl, g_hl);
    cudaGetSymbolAddress(&pT2h, g_T2h); cudaGetSymbolAddress(&pT2l, g_T2l);
    cudaGetSymbolAddress(&pW1h, g_W1h); cudaGetSymbolAddress(&pW1l, g_W1l);
    cudaGetSymbolAddress(&pW2h, g_W2h); cudaGetSymbolAddress(&pW2l, g_W2l);
    cudaGetSymbolAddress(&pb1p, g_b1p); cudaGetSymbolAddress(&pb2p, g_b2p);

    bf16 *Ab = (bf16*)pA;
    float *dinv = (float*)pDinv;
    int *perm = (int*)pPerm;
    bf16 *Xh = (bf16*)pXh, *Xl = (bf16*)pXl;
    bf16 *Th = (bf16*)pTh, *Tl = (bf16*)pTl;
    bf16 *hh = (bf16*)phh, *hl = (bf16*)phl;
    bf16 *T2h = (bf16*)pT2h, *T2l = (bf16*)pT2l;
    bf16 *W1h = (bf16*)pW1h, *W1l = (bf16*)pW1l;
    bf16 *W2h = (bf16*)pW2h, *W2l = (bf16*)pW2l;
    float *b1p = (float*)pb1p, *b2p = (float*)pb2p;

    // 0) sort att per batch
    sort_kernel<<<BB, 512>>>(att);

    // 1) adjacency (sorted space, band-pruned) + degrees
    adj_kernel<<<dim3(8, 8, BB), 256>>>(x4, Ab);
    dinv_kernel<<<dim3(BB * NN), 256>>>(Ab, dinv);

    // 2) splits (X gathered into sorted row order; W1, W2 plain) + bias pad
    {   long tot = (long)NN * FFP;
        split_kernel<<<dim3((unsigned)((tot + 255) / 256), BB), 256>>>(
            x4, Xh, Xl, NN, FF, FFP, tot, (long)NN * FF, (long)NN * FFP, perm);
    }
    {   long tot = (long)FFP * FHPN;
        split_kernel<<<dim3((unsigned)((tot + 255) / 256), 2), 256>>>(
            W1, W1h, W1l, FF, FH, FHPN, tot, (long)FF * FH, (long)FFP * FHPN, nullptr);
    }
    {   long tot = (long)FHPK * FFP;
        split_kernel<<<dim3((unsigned)((tot + 255) / 256), 2), 256>>>(
            W2, W2h, W2l, FH, FF, FFP, tot, (long)FH * FF, (long)FHPK * FFP, nullptr);
    }
    biaspad_kernel<<<dim3((FHPN + 255) / 256), 256>>>(b1, b2);

    // 3) bmm1: T = dinv ⊙ (A@Xh + A@Xl) -> split (Th, Tl)
    {
        GP p = {};
        p.A[0] = Ab; p.B[0] = Xh;
        p.A[1] = Ab; p.B[1] = Xl;
        for (int i = 0; i < 2; ++i) { p.sA[i] = (long)NN * NN; p.sB[i] = (long)NN * FFP; }
        p.nseg = 2; p.steps = NN / 16; p.ldA = NN; p.ldB = FFP;
        p.Ch = Th; p.Cl = Tl; p.sC = (long)NN * FFP; p.ldC = FFP;
        p.rowScale = dinv;
        p.bias = nullptr; p.relu = 0; p.Nlim = FFP; p.splitOut = 1;
        mma_gemm<<<dim3(FFP / 128, NN / 128, BB), 128>>>(p);
    }

    // 4) layer1: h = relu([X|T] @ [W1_0;W1_1] + b1) -> split (hh, hl)
    {
        GP p = {};
        const bf16* W10h = W1h;                      const bf16* W10l = W1l;
        const bf16* W11h = W1h + (size_t)FFP * FHPN; const bf16* W11l = W1l + (size_t)FFP * FHPN;
        p.A[0] = Xh; p.B[0] = W10h; p.A[1] = Xh; p.B[1] = W10l; p.A[2] = Xl; p.B[2] = W10h;
        p.A[3] = Th; p.B[3] = W11h; p.A[4] = Th; p.B[4] = W11l; p.A[5] = Tl; p.B[5] = W11h;
        for (int i = 0; i < 6; ++i) { p.sA[i] = (long)NN * FFP; p.sB[i] = 0; }
        p.nseg = 6; p.steps = FFP / 16; p.ldA = FFP; p.ldB = FHPN;
        p.Ch = hh; p.Cl = hl; p.sC = (long)NN * FHPN; p.ldC = FHPN;
        p.bias = b1p; p.relu = 1; p.Nlim = FHPN; p.splitOut = 1;
        mma_gemm<<<dim3(FHPN / 128, NN / 128, BB), 128>>>(p);
    }

    // 5) bmm2: T2 = dinv ⊙ (A@hh + A@hl) -> split (T2h, T2l)
    {
        GP p = {};
        p.A[0] = Ab; p.B[0] = hh;
        p.A[1] = Ab; p.B[1] = hl;
        for (int i = 0; i < 2; ++i) { p.sA[i] = (long)NN * NN; p.sB[i] = (long)NN * FHPN; }
        p.nseg = 2; p.steps = NN / 16; p.ldA = NN; p.ldB = FHPN;
        p.Ch = T2h; p.Cl = T2l; p.sC = (long)NN * FHPN; p.ldC = FHPN;
        p.rowScale = dinv;
        p.bias = nullptr; p.relu = 0; p.Nlim = FHPN; p.splitOut = 1;
        mma_gemm<<<dim3(FHPN / 128, NN / 128, BB), 128>>>(p);
    }

    // 6) layer2: out = relu([h|T2] @ [W2_0;W2_1] + b2) -> fp32 d_out, rows unsorted
    {
        GP p = {};
        const bf16* W20h = W2h;                      const bf16* W20l = W2l;
        const bf16* W21h = W2h + (size_t)FHPK * FFP; const bf16* W21l = W2l + (size_t)FHPK * FFP;
        p.A[0] = hh;  p.B[0] = W20h; p.A[1] = hh;  p.B[1] = W20l; p.A[2] = hl;  p.B[2] = W20h;
        p.A[3] = T2h; p.B[3] = W21h; p.A[4] = T2h; p.B[4] = W21l; p.A[5] = T2l; p.B[5] = W21h;
        for (int i = 0; i < 6; ++i) { p.sA[i] = (long)NN * FHPN; p.sB[i] = 0; }
        p.nseg = 6; p.steps = FHPK / 16; p.ldA = FHPN; p.ldB = FFP;
        p.Cf = out; p.sC = (long)NN * FF; p.ldC = FF;
        p.outPerm = perm;
        p.bias = b2p; p.relu = 1; p.Nlim = FF; p.splitOut = 0;
        mma_gemm<<<dim3(FFP / 128, NN / 128, BB), 128>>>(p);
    }
}

// round 7
// speedup vs baseline: 2.2354x; 1.0598x over previous
#include <cuda_runtime.h>
#include <cuda_bf16.h>
#include <cstdint>

#define BB 16
#define NN 512
#define FF 625
#define FH 937
#define FFP 640      // F padded (mult of 128)
#define FHPN 1024    // Fh padded for N-dim (mult of 128)
#define FHPK 944     // Fh padded for K-dim (mult of 16)

typedef __nv_bfloat16 bf16;

// ---------------- scratch (no allocs allowed -> device globals) -------------
__device__ bf16  g_A[(size_t)BB * NN * NN];   // adjacency 0/1 in SORTED space
__device__ float g_dinv[(size_t)BB * NN];     // 1/deg per sorted row
__device__ float g_atts[(size_t)BB * NN];     // sorted att values
__device__ int   g_perm[(size_t)BB * NN];     // perm[i] = original index of i-th smallest

__device__ bf16 g_Xh[(size_t)BB * NN * FFP],  g_Xl[(size_t)BB * NN * FFP];
__device__ bf16 g_Th[(size_t)BB * NN * FFP],  g_Tl[(size_t)BB * NN * FFP];
__device__ bf16 g_hh[(size_t)BB * NN * FHPN], g_hl[(size_t)BB * NN * FHPN];
__device__ bf16 g_T2h[(size_t)BB * NN * FHPN], g_T2l[(size_t)BB * NN * FHPN];
__device__ bf16 g_W1h[2ul * FFP * FHPN],  g_W1l[2ul * FFP * FHPN];
__device__ bf16 g_W2h[2ul * FHPK * FFP],  g_W2l[2ul * FHPK * FFP];
__device__ float g_b1p[FHPN], g_b2p[FFP];

// ---------------------------------------------------------------------------
// Kernel 0: bitonic sort of att per batch -> (sorted values, permutation).
// ---------------------------------------------------------------------------
__global__ __launch_bounds__(512) void sort_kernel(const float* __restrict__ att)
{
    __shared__ float key[NN];
    __shared__ int   idx[NN];
    const int b = blockIdx.x;
    const int t = threadIdx.x;

    key[t] = att[(size_t)b * NN + t];
    idx[t] = t;
    __syncthreads();

    for (int sz = 2; sz <= NN; sz <<= 1) {
        for (int st = sz >> 1; st > 0; st >>= 1) {
            const int p = t ^ st;
            if (p > t) {
                const bool up = ((t & sz) == 0);
                const float a = key[t], c = key[p];
                if (up ? (a > c) : (a < c)) {
                    key[t] = c; key[p] = a;
                    const int ia = idx[t]; idx[t] = idx[p]; idx[p] = ia;
                }
            }
            __syncthreads();
        }
    }
    g_atts[(size_t)b * NN + t] = key[t];
    g_perm[(size_t)b * NN + t] = idx[t];
}

// ---------------------------------------------------------------------------
// Kernel 1: thresholded adjacency in sorted space.
//  - att-band pruning: tiles with no possible att overlap write zeros.
//  - symmetry: only bi<=bj tiles compute; mirror tile written by transpose.
//    Bit-identical: same k-order, |a-b| == |b-a|.
// ---------------------------------------------------------------------------
__global__ __launch_bounds__(256) void adj_kernel(
    const float* __restrict__ X, bf16* __restrict__ A)
{
    const int b  = blockIdx.z;
    const int bi = blockIdx.y;
    const int bj = blockIdx.x;
    if (bj < bi) return;                     // mirror handled by (bi,bj)
    const int i0 = bi * 64;
    const int j0 = bj * 64;
    const float* as = g_atts + (size_t)b * NN;
    const int* permB = g_perm + (size_t)b * NN;
    bf16* Ab = A + (size_t)b * NN * NN;
    const int tid = threadIdx.x;

    // ---- prune: sorted att -> valid j's contiguous; conservative epsilon ----
    if (as[j0] > as[i0 + 63] + 0.0501f || as[j0 + 63] < as[i0] - 0.0501f) {
        const int r = tid >> 2, c4 = tid & 3;
        float4 z = make_float4(0.f, 0.f, 0.f, 0.f);
        float4* row = (float4*)(Ab + (size_t)(i0 + r) * NN + j0);
        row[c4 * 2] = z;
        row[c4 * 2 + 1] = z;
        if (bi != bj) {
            float4* rowT = (float4*)(Ab + (size_t)(j0 + r) * NN + i0);
            rowT[c4 * 2] = z;
            rowT[c4 * 2 + 1] = z;
        }
        return;
    }

    __shared__ __align__(16) char sbuf[17408];
    float (*sXi)[68] = (float (*)[68])sbuf;
    float (*sXj)[68] = (float (*)[68])(sbuf + 8704);

    const float* Xb = X + (size_t)b * NN * FF;
    const int tx = tid & 15;
    const int ty = tid >> 4;

    float acc[4][4];
#pragma unroll
    for (int r = 0; r < 4; ++r)
#pragma unroll
        for (int c = 0; c < 4; ++c) acc[r][c] = 0.f;

    const int lk = tid & 31;
    const int lr = tid >> 5;

    int piR[8], pjR[8];
#pragma unroll
    for (int r = 0; r < 8; ++r) {
        piR[r] = permB[i0 + lr + r * 8];
        pjR[r] = permB[j0 + lr + r * 8];
    }

    for (int k0 = 0; k0 < FF; k0 += 32) {
#pragma unroll
        for (int r = 0; r < 8; ++r) {
            const int row = lr + r * 8;
            const int k = k0 + lk;
            float vi = 0.f, vj = 0.f;
            if (k < FF) {
                vi = Xb[(size_t)piR[r] * FF + k];
                vj = Xb[(size_t)pjR[r] * FF + k];
            }
            sXi[lk][row] = vi;
            sXj[lk][row] = vj;
        }
        __syncthreads();
#pragma unroll
        for (int kk = 0; kk < 32; ++kk) {
            const float4 av = *(const float4*)&sXi[kk][ty * 4];
            const float4 bv = *(const float4*)&sXj[kk][tx * 4];
            const float a_[4] = {av.x, av.y, av.z, av.w};
            const float b_[4] = {bv.x, bv.y, bv.z, bv.w};
#pragma unroll
            for (int r = 0; r < 4; ++r)
#pragma unroll
                for (int c = 0; c < 4; ++c)
                    acc[r][c] += fabsf(a_[r] - b_[c]);
        }
        __syncthreads();
    }

    float ai[4], aj[4];
#pragma unroll
    for (int r = 0; r < 4; ++r) ai[r] = as[i0 + ty * 4 + r];
#pragma unroll
    for (int c = 0; c < 4; ++c) aj[c] = as[j0 + tx * 4 + c];

    unsigned short bits[4][4];
#pragma unroll
    for (int r = 0; r < 4; ++r) {
        const int i = i0 + ty * 4 + r;
#pragma unroll
        for (int c = 0; c < 4; ++c) {
            const int j = j0 + tx * 4 + c;
            const bool keep = (acc[r][c] <= 180.0f && fabsf(ai[r] - aj[c]) <= 0.05f);
            bits[r][c] = keep ? 0x3F80 : 0;       // bf16 1.0 / 0.0
            *(unsigned short*)&Ab[(size_t)i * NN + j] = bits[r][c];
        }
    }

    if (bi != bj) {
        // transpose through smem, then coalesced row writes of the mirror tile
        unsigned short (*sT)[66] = (unsigned short (*)[66])sbuf;
        __syncthreads();
#pragma unroll
        for (int r = 0; r < 4; ++r)
#pragma unroll
            for (int c = 0; c < 4; ++c)
                sT[tx * 4 + c][ty * 4 + r] = bits[r][c];
        __syncthreads();
        const int jr = tid >> 2;
        const int cs = (tid & 3) * 16;
        bf16* dst = Ab + (size_t)(j0 + jr) * NN + i0 + cs;
#pragma unroll
        for (int q = 0; q < 8; ++q) {
            uint32_t v = (uint32_t)sT[jr][cs + 2 * q] |
                         ((uint32_t)sT[jr][cs + 2 * q + 1] << 16);
            *(uint32_t*)(dst + 2 * q) = v;
        }
    }
}

// ---------------------------------------------------------------------------
// Kernel 2: dinv[row] = 1 / rowsum(A).
// ---------------------------------------------------------------------------
__global__ __launch_bounds__(256) void dinv_kernel(
    const bf16* __restrict__ A, float* __restrict__ dinv)
{
    const size_t row = blockIdx.x;
    const bf16* p = A + row * NN;
    const int t = threadIdx.x;

    float v = __bfloat162float(p[t]) + __bfloat162float(p[t + 256]);
#pragma unroll
    for (int o = 16; o; o >>= 1) v += __shfl_down_sync(0xffffffffu, v, o);

    __shared__ float swarp[8];
    if ((t & 31) == 0) swarp[t >> 5] = v;
    __syncthreads();
    if (t == 0) {
        float d = 0.f;
#pragma unroll
        for (int w = 0; w < 8; ++w) d += swarp[w];
        dinv[row] = 1.0f / d;
    }
}

// ---------------------------------------------------------------------------
// Split fp32 -> (hi, lo) bf16, zero-padded; optional row gather via perm.
// ---------------------------------------------------------------------------
__global__ __launch_bounds__(256) void split_kernel(
    const float* __restrict__ src, bf16* __restrict__ dh, bf16* __restrict__ dl,
    int R, int C, int Cp, long totalP, long sStride, long dStride,
    const int* __restrict__ perm)
{
    long idx = (long)blockIdx.x * 256 + threadIdx.x;
    if (idx >= totalP) return;
    const int b = blockIdx.y;
    const int r = (int)(idx / Cp);
    const int c = (int)(idx % Cp);
    float v = 0.f;
    if (r < R && c < C) {
        const int sr = perm ? perm[(long)b * NN + r] : r;
        v = src[(long)b * sStride + (long)sr * C + c];
    }
    bf16 hi = __float2bfloat16(v);
    float lo = v - __bfloat162float(hi);
    dh[(long)b * dStride + idx] = hi;
    dl[(long)b * dStride + idx] = __float2bfloat16(lo);
}

__global__ void biaspad_kernel(const float* __restrict__ b1, const float* __restrict__ b2)
{
    int t = blockIdx.x * 256 + threadIdx.x;
    if (t < FHPN) g_b1p[t] = (t < FH) ? b1[t] : 0.f;
    if (t < FFP)  g_b2p[t] = (t < FF) ? b2[t] : 0.f;
}

// ---------------------------------------------------------------------------
// Tensor-core GEMM: 128x128 block, 4 warps (warp tile 64x64), 128 threads,
// 4-stage cp.async pipeline. C = op(rowScale ⊙ ΣA_seg@B_seg + bias).
// If p.atts != null (bmm with 0/1 adjacency A): restrict K-steps to the
// att band of this m-block — skipped products are exactly zero.
// ---------------------------------------------------------------------------
struct GP {
    const bf16* A[6];
    const bf16* B[6];
    long sA[6], sB[6];
    int  nseg, steps;
    int  ldA, ldB;
    float* Cf; bf16* Ch; bf16* Cl;
    long sC; int ldC;
    const float* bias;
    const float* rowScale;
    const int* outPerm;
    const float* atts;       // sorted att (stride NN per batch) -> band-K pruning
    int relu, Nlim, splitOut;
};

__device__ __forceinline__ void cp16(uint32_t dst, const void* src) {
    asm volatile("cp.async.cg.shared.global [%0], [%1], 16;\n" :: "r"(dst), "l"(src));
}
__device__ __forceinline__ void ldsm4(uint32_t* r, uint32_t addr) {
    asm volatile("ldmatrix.sync.aligned.m8n8.x4.shared.b16 {%0,%1,%2,%3}, [%4];\n"
                 : "=r"(r[0]), "=r"(r[1]), "=r"(r[2]), "=r"(r[3]) : "r"(addr));
}
__device__ __forceinline__ void ldsm4t(uint32_t* r, uint32_t addr) {
    asm volatile("ldmatrix.sync.aligned.m8n8.x4.trans.shared.b16 {%0,%1,%2,%3}, [%4];\n"
                 : "=r"(r[0]), "=r"(r[1]), "=r"(r[2]), "=r"(r[3]) : "r"(addr));
}
__device__ __forceinline__ void mma16816(float* d, const uint32_t* a, uint32_t b0, uint32_t b1) {
    asm volatile(
        "mma.sync.aligned.m16n8k16.row.col.f32.bf16.bf16.f32 "
        "{%0,%1,%2,%3}, {%4,%5,%6,%7}, {%8,%9}, {%0,%1,%2,%3};\n"
        : "+f"(d[0]), "+f"(d[1]), "+f"(d[2]), "+f"(d[3])
        : "r"(a[0]), "r"(a[1]), "r"(a[2]), "r"(a[3]), "r"(b0), "r"(b1));
}

__global__ __launch_bounds__(128, 2) void mma_gemm(GP p)
{
    __shared__ __align__(128) char smem[32768];
    const uint32_t sbase = (uint32_t)__cvta_generic_to_shared(smem);

    const int tid  = threadIdx.x;
    const int lane = tid & 31;
    const int warp = tid >> 5;
    const int b  = blockIdx.z;
    const int m0 = blockIdx.y * 128;
    const int n0 = blockIdx.x * 128;
    const int wm = (warp & 1) * 64;
    const int wn = (warp >> 1) * 64;

    // band-K restriction for adjacency GEMMs
    int sStart = 0, sEnd = p.steps;
    if (p.atts) {
        const float* as = p.atts + (long)b * NN;
        const float lo = as[m0] - 0.0501f;
        const float hi = as[m0 + 127] + 0.0501f;
        int l = 0, r = NN;
        while (l < r) { int mid = (l + r) >> 1; if (as[mid] < lo) l = mid + 1; else r = mid; }
        const int kLo = l;
        l = 0; r = NN;
        while (l < r) { int mid = (l + r) >> 1; if (as[mid] <= hi) l = mid + 1; else r = mid; }
        const int kHi = l;                 // exclusive
        sStart = kLo >> 4;
        sEnd   = (kHi + 15) >> 4;
    }
    const int segSteps = sEnd - sStart;
    const int total = p.nseg * segSteps;

    float acc[4][8][4];
#pragma unroll
    for (int i = 0; i < 4; ++i)
#pragma unroll
        for (int j = 0; j < 8; ++j)
#pragma unroll
            for (int k = 0; k < 4; ++k) acc[i][j][k] = 0.f;

    const int ar = tid;
    const int bk = tid >> 4;
    const int bc = tid & 15;
    const uint32_t aDst0 = (uint32_t)((ar * 2 + (0 ^ ((ar >> 2) & 1))) * 16);
    const uint32_t aDst1 = (uint32_t)((ar * 2 + (1 ^ ((ar >> 2) & 1))) * 16);
    const uint32_t bDst0 = (uint32_t)(4096 + (bk * 16 + (bc ^ (bk & 7))) * 16);
    const uint32_t bDst1 = bDst0 + 2048;

    uint32_t aLd[4], bLd[4];
#pragma unroll
    for (int f = 0; f < 4; ++f) {
        const int r = wm + f * 16 + (lane & 15);
        const int c = (lane >> 4) & 1;
        aLd[f] = (uint32_t)((r * 2 + (c ^ ((r >> 2) & 1))) * 16);
    }
#pragma unroll
    for (int g = 0; g < 4; ++g) {
        const int kk = lane & 15;
        const int cn = (wn >> 3) + g * 2 + ((lane >> 4) & 1);
        bLd[g] = (uint32_t)(4096 + (kk * 16 + (cn ^ (kk & 7))) * 16);
    }

    const long aOff = (long)(m0 + ar) * p.ldA;
    const long bOff = (long)bk * p.ldB + n0 + bc * 8;
    const bf16* Ag = p.A[0] + (long)b * p.sA[0] + aOff;
    const bf16* Bg = p.B[0] + (long)b * p.sB[0] + bOff;
    int pSeg = 0, pKs = 0;

    auto issue = [&](int stage) {
        const uint32_t base = sbase + (uint32_t)stage * 8192;
        const long ks = (long)(sStart + pKs);
        const bf16* as_ = Ag + ks * 16;
        const bf16* bs_ = Bg + ks * 16 * p.ldB;
        cp16(base + aDst0, as_);
        cp16(base + aDst1, as_ + 8);
        cp16(base + bDst0, bs_);
        cp16(base + bDst1, bs_ + (long)8 * p.ldB);
        if (++pKs == segSteps) {
            pKs = 0;
            if (++pSeg < p.nseg) {
                Ag = p.A[pSeg] + (long)b * p.sA[pSeg] + aOff;
                Bg = p.B[pSeg] + (long)b * p.sB[pSeg] + bOff;
            }
        }
    };

#pragma unroll
    for (int i = 0; i < 3; ++i) {   // total >= 16 for all launches
        issue(i);
        asm volatile("cp.async.commit_group;\n");
    }

    for (int s = 0; s < total; ++s) {
        asm volatile("cp.async.wait_group 2;\n");
        __syncthreads();

        const uint32_t so = (uint32_t)((s & 3) * 8192);
        uint32_t afr[4][4], bfr[4][4];
#pragma unroll
        for (int f = 0; f < 4; ++f) ldsm4(afr[f], sbase + so + aLd[f]);
#pragma unroll
        for (int g = 0; g < 4; ++g) ldsm4t(bfr[g], sbase + so + bLd[g]);

        if (s + 3 < total) issue((s + 3) & 3);
        asm volatile("cp.async.commit_group;\n");

#pragma unroll
        for (int mf = 0; mf < 4; ++mf)
#pragma unroll
            for (int nf = 0; nf < 8; ++nf) {
                const uint32_t* bb = bfr[nf >> 1];
                const int sub = (nf & 1) * 2;
                mma16816(acc[mf][nf], afr[mf], bb[sub], bb[sub + 1]);
            }
    }

    // -------- epilogue --------
    const float* rsB = p.rowScale ? (p.rowScale + (long)b * NN) : nullptr;
    const int* opB = p.outPerm ? (p.outPerm + (long)b * NN) : nullptr;
    const int row0 = m0 + wm;
    const int col0 = n0 + wn;
#pragma unroll
    for (int mf = 0; mf < 4; ++mf) {
        const int m = row0 + mf * 16 + (lane >> 2);
        const float rs0 = rsB ? rsB[m] : 1.f;
        const float rs1 = rsB ? rsB[m + 8] : 1.f;
#pragma unroll
        for (int nf = 0; nf < 8; ++nf) {
            const int n = col0 + nf * 8 + (lane & 3) * 2;
            float v[4] = {acc[mf][nf][0] * rs0, acc[mf][nf][1] * rs0,
                          acc[mf][nf][2] * rs1, acc[mf][nf][3] * rs1};
            if (p.bias) {
                const float bz0 = p.bias[n], bz1 = p.bias[n + 1];
                v[0] += bz0; v[1] += bz1; v[2] += bz0; v[3] += bz1;
            }
            if (p.relu) {
#pragma unroll
                for (int q = 0; q < 4; ++q) v[q] = fmaxf(v[q], 0.f);
            }
            if (p.splitOut) {
#pragma unroll
                for (int q = 0; q < 4; ++q) {
                    const int mm = m + (q >> 1) * 8;
                    const int nn = n + (q & 1);
                    const long off = (long)b * p.sC + (long)mm * p.ldC + nn;
                    bf16 hi = __float2bfloat16(v[q]);
                    p.Ch[off] = hi;
                    p.Cl[off] = __float2bfloat16(v[q] - __bfloat162float(hi));
                }
            } else {
#pragma unroll
                for (int q = 0; q < 4; ++q) {
                    const int mm = m + (q >> 1) * 8;
                    const int nn = n + (q & 1);
                    if (nn < p.Nlim) {
                        const int mo = opB ? opB[mm] : mm;
                        p.Cf[(long)b * p.sC + (long)mo * p.ldC + nn] = v[q];
                    }
                }
            }
        }
    }
}

// ---------------------------------------------------------------------------
extern "C" void kernel_launch(void* const* d_in, const int* in_sizes, int n_in,
                              void* d_out, int out_size)
{
    const float* x4  = (const float*)d_in[0];
    const float* att = (const float*)d_in[1];
    const float* W1  = (const float*)d_in[2];
    const float* b1  = (const float*)d_in[3];
    const float* W2  = (const float*)d_in[4];
    const float* b2  = (const float*)d_in[5];
    float* out = (float*)d_out;

    void *pA, *pDinv, *pPerm, *pAtts, *pXh, *pXl, *pTh, *pTl, *phh, *phl, *pT2h, *pT2l;
    void *pW1h, *pW1l, *pW2h, *pW2l, *pb1p, *pb2p;
    cudaGetSymbolAddress(&pA, g_A);
    cudaGetSymbolAddress(&pDinv, g_dinv);
    cudaGetSymbolAddress(&pPerm, g_perm);
    cudaGetSymbolAddress(&pAtts, g_atts);
    cudaGetSymbolAddress(&pXh, g_Xh);  cudaGetSymbolAddress(&pXl, g_Xl);
    cudaGetSymbolAddress(&pTh, g_Th);  cudaGetSymbolAddress(&pTl, g_Tl);
    cudaGetSymbolAddress(&phh, g_hh);  cudaGetSymbolAddress(&phl, g_hl);
    cudaGetSymbolAddress(&pT2h, g_T2h); cudaGetSymbolAddress(&pT2l, g_T2l);
    cudaGetSymbolAddress(&pW1h, g_W1h); cudaGetSymbolAddress(&pW1l, g_W1l);
    cudaGetSymbolAddress(&pW2h, g_W2h); cudaGetSymbolAddress(&pW2l, g_W2l);
    cudaGetSymbolAddress(&pb1p, g_b1p); cudaGetSymbolAddress(&pb2p, g_b2p);

    bf16 *Ab = (bf16*)pA;
    float *dinv = (float*)pDinv;
    int *perm = (int*)pPerm;
    float *atts = (float*)pAtts;
    bf16 *Xh = (bf16*)pXh, *Xl = (bf16*)pXl;
    bf16 *Th = (bf16*)pTh, *Tl = (bf16*)pTl;
    bf16 *hh = (bf16*)phh, *hl = (bf16*)phl;
    bf16 *T2h = (bf16*)pT2h, *T2l = (bf16*)pT2l;
    bf16 *W1h = (bf16*)pW1h, *W1l = (bf16*)pW1l;
    bf16 *W2h = (bf16*)pW2h, *W2l = (bf16*)pW2l;
    float *b1p = (float*)pb1p, *b2p = (float*)pb2p;

    // launch order chosen so ncu -s 5 lands on bmm1's mma_gemm
    sort_kernel<<<BB, 512>>>(att);                               // 0
    adj_kernel<<<dim3(8, 8, BB), 256>>>(x4, Ab);                 // 1
    dinv_kernel<<<dim3(BB * NN), 256>>>(Ab, dinv);               // 2
    {   long tot = (long)NN * FFP;                               // 3: X split (sorted gather)
        split_kernel<<<dim3((unsigned)((tot + 255) / 256), BB), 256>>>(
            x4, Xh, Xl, NN, FF, FFP, tot, (long)NN * FF, (long)NN * FFP, perm);
    }
    {   long tot = (long)FFP * FHPN;                             // 4: W1 split
        split_kernel<<<dim3((unsigned)((tot + 255) / 256), 2), 256>>>(
            W1, W1h, W1l, FF, FH, FHPN, tot, (long)FF * FH, (long)FFP * FHPN, nullptr);
    }

    // 5: bmm1: T = dinv ⊙ (A@Xh + A@Xl) -> split (Th, Tl)   [band-K pruned]
    {
        GP p = {};
        p.A[0] = Ab; p.B[0] = Xh;
        p.A[1] = Ab; p.B[1] = Xl;
        for (int i = 0; i < 2; ++i) { p.sA[i] = (long)NN * NN; p.sB[i] = (long)NN * FFP; }
        p.nseg = 2; p.steps = NN / 16; p.ldA = NN; p.ldB = FFP;
        p.Ch = Th; p.Cl = Tl; p.sC = (long)NN * FFP; p.ldC = FFP;
        p.rowScale = dinv; p.atts = atts;
        p.bias = nullptr; p.relu = 0; p.Nlim = FFP; p.splitOut = 1;
        mma_gemm<<<dim3(FFP / 128, NN / 128, BB), 128>>>(p);
    }

    {   long tot = (long)FHPK * FFP;                             // 6: W2 split
        split_kernel<<<dim3((unsigned)((tot + 255) / 256), 2), 256>>>(
            W2, W2h, W2l, FH, FF, FFP, tot, (long)FH * FF, (long)FHPK * FFP, nullptr);
    }
    biaspad_kernel<<<dim3((FHPN + 255) / 256), 256>>>(b1, b2);   // 7

    // 8: layer1: h = relu([X|T] @ [W1_0;W1_1] + b1) -> split (hh, hl)
    {
        GP p = {};
        const bf16* W10h = W1h;                      const bf16* W10l = W1l;
        const bf16* W11h = W1h + (size_t)FFP * FHPN; const bf16* W11l = W1l + (size_t)FFP * FHPN;
        p.A[0] = Xh; p.B[0] = W10h; p.A[1] = Xh; p.B[1] = W10l; p.A[2] = Xl; p.B[2] = W10h;
        p.A[3] = Th; p.B[3] = W11h; p.A[4] = Th; p.B[4] = W11l; p.A[5] = Tl; p.B[5] = W11h;
        for (int i = 0; i < 6; ++i) { p.sA[i] = (long)NN * FFP; p.sB[i] = 0; }
        p.nseg = 6; p.steps = FFP / 16; p.ldA = FFP; p.ldB = FHPN;
        p.Ch = hh; p.Cl = hl; p.sC = (long)NN * FHPN; p.ldC = FHPN;
        p.bias = b1p; p.relu = 1; p.Nlim = FHPN; p.splitOut = 1;
        mma_gemm<<<dim3(FHPN / 128, NN / 128, BB), 128>>>(p);
    }

    // 9: bmm2: T2 = dinv ⊙ (A@hh + A@hl) -> split (T2h, T2l)   [band-K pruned]
    {
        GP p = {};
        p.A[0] = Ab; p.B[0] = hh;
        p.A[1] = Ab; p.B[1] = hl;
        for (int i = 0; i < 2; ++i) { p.sA[i] = (long)NN * NN; p.sB[i] = (long)NN * FHPN; }
        p.nseg = 2; p.steps = NN / 16; p.ldA = NN; p.ldB = FHPN;
        p.Ch = T2h; p.Cl = T2l; p.sC = (long)NN * FHPN; p.ldC = FHPN;
        p.rowScale = dinv; p.atts = atts;
        p.bias = nullptr; p.relu = 0; p.Nlim = FHPN; p.splitOut = 1;
        mma_gemm<<<dim3(FHPN / 128, NN / 128, BB), 128>>>(p);
    }

    // 10: layer2: out = relu([h|T2] @ [W2_0;W2_1] + b2) -> fp32, rows un-permuted
    {
        GP p = {};
        const bf16* W20h = W2h;                      const bf16* W20l = W2l;
        const bf16* W21h = W2h + (size_t)FHPK * FFP; const bf16* W21l = W2l + (size_t)FHPK * FFP;
        p.A[0] = hh;  p.B[0] = W20h; p.A[1] = hh;  p.B[1] = W20l; p.A[2] = hl;  p.B[2] = W20h;
        p.A[3] = T2h; p.B[3] = W21h; p.A[4] = T2h; p.B[4] = W21l; p.A[5] = T2l; p.B[5] = W21h;
        for (int i = 0; i < 6; ++i) { p.sA[i] = (long)NN * FHPN; p.sB[i] = 0; }
        p.nseg = 6; p.steps = FHPK / 16; p.ldA = FHPN; p.ldB = FFP;
        p.Cf = out; p.sC = (long)NN * FF; p.ldC = FF;
        p.outPerm = perm;
        p.bias = b2p; p.relu = 1; p.Nlim = FF; p.splitOut = 0;
        mma_gemm<<<dim3(FFP / 128, NN / 128, BB), 128>>>(p);
    }
}